// round 12
// baseline (speedup 1.0000x reference)
#include <cuda_runtime.h>
#include <cuda_fp16.h>
#include <cstdint>

#define NN   131072
#define EE   2097152
#define FF   32
#define HH   128
#define RR   10
#define BB   4
#define LL   3
#define OUTD 8

#define TM   64               // layer-kernel block rows (dst nodes)
#define SAP  648              // sA k-stride in halves (640 + 8 pad)
#define SBP  24               // sB row stride in halves (16 used + 8 pad)
#define SB_BUF (128 * SBP)    // halves per 16-k B buffer (3072)
#define NBUF 5                // cp.async pipeline depth
#define SCP  132              // sC row stride in floats
#define NC16 40               // 16-wide K chunks (640 total)
#define SMEM_LAYER (TM * SAP * 2 + NBUF * SB_BUF * 2)   // 113664 B
#define SMEM_HEAD  (128 * SCP * 4)                      // 67584 B
#define PROBE_BLOCKS 512

// ---------------- device scratch ----------------
__device__ float  g_h  [(size_t)NN * HH];
__device__ float  g_t  [(size_t)NN * HH];
__device__ __half g_hh0[(size_t)NN * HH];   // fp16 mirror (ping)
__device__ __half g_hh1[(size_t)NN * HH];   // fp16 mirror (pong)
__device__ __half g_wB [(size_t)LL * NC16 * 128 * 16]; // staged fp16 weights
__device__ float  g_cnt[NN * RR];
__device__ int    g_deg[NN];
__device__ int    g_row[NN + 1];
__device__ int    g_bsum[512];
__device__ int    g_cursor[NN];
__device__ int2   g_meta[EE];          // dst-sorted {src|rel<<20, bits(1/cnt)}
__device__ int    g_is64;
__device__ float  g_probe   [(size_t)PROBE_BLOCKS * TM * HH];  // probe scratch
__device__ __half g_probe_hh[(size_t)PROBE_BLOCKS * TM * HH];

// ---------------- helpers ----------------
__device__ __forceinline__ float tf32r(float x) {
    uint32_t o;
    asm("cvt.rna.tf32.f32 %0, %1;" : "=r"(o) : "f"(x));
    return __uint_as_float(o);
}

__device__ __forceinline__ void mma_tf32(float& c0, float& c1, float& c2, float& c3,
                                         uint32_t a0, uint32_t a1, uint32_t a2, uint32_t a3,
                                         uint32_t b0, uint32_t b1) {
    asm volatile(
        "mma.sync.aligned.m16n8k8.row.col.f32.tf32.tf32.f32 "
        "{%0,%1,%2,%3}, {%4,%5,%6,%7}, {%8,%9}, {%0,%1,%2,%3};"
        : "+f"(c0), "+f"(c1), "+f"(c2), "+f"(c3)
        : "r"(a0), "r"(a1), "r"(a2), "r"(a3), "r"(b0), "r"(b1));
}

__device__ __forceinline__ void mma_f16(float* c,
                                        uint32_t a0, uint32_t a1, uint32_t a2, uint32_t a3,
                                        uint32_t b0, uint32_t b1) {
    asm volatile(
        "mma.sync.aligned.m16n8k16.row.col.f32.f16.f16.f32 "
        "{%0,%1,%2,%3}, {%4,%5,%6,%7}, {%8,%9}, {%0,%1,%2,%3};"
        : "+f"(c[0]), "+f"(c[1]), "+f"(c[2]), "+f"(c[3])
        : "r"(a0), "r"(a1), "r"(a2), "r"(a3), "r"(b0), "r"(b1));
}

__device__ __forceinline__ void cp16(uint32_t dst_smem, const void* src) {
    asm volatile("cp.async.cg.shared.global [%0], [%1], 16;"
                 :: "r"(dst_smem), "l"(src) : "memory");
}
#define CP_COMMIT()  asm volatile("cp.async.commit_group;" ::: "memory")
#define CP_WAIT3()   asm volatile("cp.async.wait_group 3;" ::: "memory")

// ---------------- dtype detect ----------------
__global__ void k_detect(const int* __restrict__ ei) {
    __shared__ int cnt;
    if (threadIdx.x == 0) cnt = 0;
    __syncthreads();
    if (ei[threadIdx.x * 2 + 1] != 0) atomicAdd(&cnt, 1);
    __syncthreads();
    if (threadIdx.x == 0) g_is64 = (cnt == 0) ? 1 : 0;
}

__global__ void k_zero_cnt() {
    int i = blockIdx.x * blockDim.x + threadIdx.x;
    if (i < NN * RR) g_cnt[i] = 0.0f;
    if (i < NN) g_deg[i] = 0;
}

// ---------------- decode + count ----------------
__global__ void k_prep_count(const void* __restrict__ ei_raw, const void* __restrict__ et_raw) {
    int e = blockIdx.x * blockDim.x + threadIdx.x;
    if (e >= EE) return;
    int d, t;
    if (g_is64) {
        const long long* ei = (const long long*)ei_raw;
        const long long* et = (const long long*)et_raw;
        d = (int)ei[(size_t)EE + e];
        t = (int)et[e];
    } else {
        const int* ei = (const int*)ei_raw;
        const int* et = (const int*)et_raw;
        d = ei[EE + e];
        t = et[e];
    }
    atomicAdd(&g_cnt[d * RR + t], 1.0f);
    atomicAdd(&g_deg[d], 1);
}

// ================= PROBE: instruction-faithful k_layer replica, synthetic CSR =================
// Launched 4th so ncu (-s 5 -c 1) captures it. Degree=16/node, hashed src -> same
// random-gather statistics as the real aggregation. Writes only probe scratch.
__global__ void __launch_bounds__(256, 2) k_probe() {
    extern __shared__ __align__(16) char dyn[];
    __half* sA = (__half*)dyn;
    __half* sB = (__half*)(dyn + TM * SAP * 2);
    float*  sC = (float*)dyn;
    __shared__ float s_comp[RR * BB];

    const __half* hh_in = g_hh0;
    const __half* wB_l  = g_wB;

    int tid = threadIdx.x, warp = tid >> 5, lane = tid & 31;
    int m0 = blockIdx.x * TM;
    if (tid < RR * BB) s_comp[tid] = 0.03f * tid;

    uint32_t smem_u32;
    asm("{ .reg .u64 t; cvta.to.shared.u64 t, %1; cvt.u32.u64 %0, t; }"
        : "=r"(smem_u32) : "l"(dyn));
    uint32_t sB32 = smem_u32 + TM * SAP * 2;

    int nB = tid >> 1, hp = tid & 1;
    uint32_t dst_off = (uint32_t)(nB * SBP + hp * 8) * 2;
#pragma unroll
    for (int c = 0; c < 4; c++) {
        cp16(sB32 + c * SB_BUF * 2 + dst_off,
             wB_l + ((size_t)c * 128 + nB) * 16 + hp * 8);
        CP_COMMIT();
    }

    for (int i = tid; i < TM * 16; i += 256) {
        int m = i >> 4, c8 = i & 15;
        *(uint4*)(sA + m * SAP + 512 + c8 * 8) =
            ((const uint4*)(hh_in + (size_t)(m0 + m) * HH))[c8];
    }
    __syncthreads();

#define ACC_EDGE(mt, r)                                                       \
    {                                                                         \
        int   t_  = (mt.x >> 20) & 7;                                         \
        float iv_ = __int_as_float(mt.y);                                     \
        float c0 = s_comp[t_ * BB + 0] * iv_;                                 \
        float c1 = s_comp[t_ * BB + 1] * iv_;                                 \
        float c2 = s_comp[t_ * BB + 2] * iv_;                                 \
        float c3 = s_comp[t_ * BB + 3] * iv_;                                 \
        float2 p0 = __half22float2(*(__half2*)&r.x);                          \
        float2 p1 = __half22float2(*(__half2*)&r.y);                          \
        a0.x += c0 * p0.x; a0.y += c0 * p0.y; a0.z += c0 * p1.x; a0.w += c0 * p1.y; \
        a1.x += c1 * p0.x; a1.y += c1 * p0.y; a1.z += c1 * p1.x; a1.w += c1 * p1.y; \
        a2.x += c2 * p0.x; a2.y += c2 * p0.y; a2.z += c2 * p1.x; a2.w += c2 * p1.y; \
        a3.x += c3 * p0.x; a3.y += c3 * p0.y; a3.z += c3 * p1.x; a3.w += c3 * p1.y; \
    }
#define HASH_SRC(node, e) ((int)((((uint32_t)(node)) * 2654435761u + ((uint32_t)(e)) * 2246822519u) & (NN - 1)))

    for (int ii = 0; ii < 8; ii++) {
        int m = warp * 8 + ii;
        int node = m0 + m;
        float4 a0 = make_float4(0.f, 0.f, 0.f, 0.f);
        float4 a1 = a0, a2 = a0, a3 = a0;
#pragma unroll 1
        for (int e = 0; e < 16; e += 4) {
            int base = (node * 16 + e) & (EE - 1);
            int2 m0_ = __ldg(&g_meta[base + 0]);
            int2 m1_ = __ldg(&g_meta[base + 1]);
            int2 m2_ = __ldg(&g_meta[base + 2]);
            int2 m3_ = __ldg(&g_meta[base + 3]);
            int s0 = HASH_SRC(node, e + 0) ^ (m0_.x & 1);
            int s1 = HASH_SRC(node, e + 1) ^ (m1_.x & 1);
            int s2 = HASH_SRC(node, e + 2) ^ (m2_.x & 1);
            int s3 = HASH_SRC(node, e + 3) ^ (m3_.x & 1);
            uint2 r0 = __ldg((const uint2*)(hh_in + (size_t)s0 * HH) + lane);
            uint2 r1 = __ldg((const uint2*)(hh_in + (size_t)s1 * HH) + lane);
            uint2 r2 = __ldg((const uint2*)(hh_in + (size_t)s2 * HH) + lane);
            uint2 r3 = __ldg((const uint2*)(hh_in + (size_t)s3 * HH) + lane);
            ACC_EDGE(m0_, r0);
            ACC_EDGE(m1_, r1);
            ACC_EDGE(m2_, r2);
            ACC_EDGE(m3_, r3);
        }
        __half* dst = sA + m * SAP + 4 * lane;
        *(__half2*)(dst + 0 * 128 + 0) = __floats2half2_rn(a0.x, a0.y);
        *(__half2*)(dst + 0 * 128 + 2) = __floats2half2_rn(a0.z, a0.w);
        *(__half2*)(dst + 1 * 128 + 0) = __floats2half2_rn(a1.x, a1.y);
        *(__half2*)(dst + 1 * 128 + 2) = __floats2half2_rn(a1.z, a1.w);
        *(__half2*)(dst + 2 * 128 + 0) = __floats2half2_rn(a2.x, a2.y);
        *(__half2*)(dst + 2 * 128 + 2) = __floats2half2_rn(a2.z, a2.w);
        *(__half2*)(dst + 3 * 128 + 0) = __floats2half2_rn(a3.x, a3.y);
        *(__half2*)(dst + 3 * 128 + 2) = __floats2half2_rn(a3.z, a3.w);
    }
#undef ACC_EDGE
#undef HASH_SRC
    __syncthreads();

    int wm = warp & 1, wn = warp >> 1;
    int g = lane >> 2, t = lane & 3;
    float acc[2][4][4];
#pragma unroll
    for (int i = 0; i < 2; i++)
#pragma unroll
        for (int j = 0; j < 4; j++)
#pragma unroll
            for (int c = 0; c < 4; c++) acc[i][j][c] = 0.f;

    int bufr = 0;
    for (int kc = 0; kc < NC16; kc++) {
        CP_WAIT3();
        __syncthreads();
        int bufw = bufr + 4; if (bufw >= NBUF) bufw -= NBUF;
        if (kc + 4 < NC16)
            cp16(sB32 + bufw * SB_BUF * 2 + dst_off,
                 wB_l + ((size_t)(kc + 4) * 128 + nB) * 16 + hp * 8);
        CP_COMMIT();

        const __half* bb = sB + bufr * SB_BUF;
        int ka = kc * 16 + 2 * t;
        uint32_t Bf[4][2];
#pragma unroll
        for (int ni = 0; ni < 4; ni++) {
            int n = wn * 32 + ni * 8 + g;
            Bf[ni][0] = *(const uint32_t*)&bb[n * SBP + 2 * t];
            Bf[ni][1] = *(const uint32_t*)&bb[n * SBP + 2 * t + 8];
        }
#pragma unroll
        for (int mi = 0; mi < 2; mi++) {
            int R = wm * 32 + mi * 16 + g;
            uint32_t A0 = *(const uint32_t*)&sA[R * SAP + ka];
            uint32_t A1 = *(const uint32_t*)&sA[(R + 8) * SAP + ka];
            uint32_t A2 = *(const uint32_t*)&sA[R * SAP + ka + 8];
            uint32_t A3 = *(const uint32_t*)&sA[(R + 8) * SAP + ka + 8];
#pragma unroll
            for (int ni = 0; ni < 4; ni++)
                mma_f16(acc[mi][ni], A0, A1, A2, A3, Bf[ni][0], Bf[ni][1]);
        }
        bufr++; if (bufr == NBUF) bufr = 0;
    }
    __syncthreads();

#pragma unroll
    for (int mi = 0; mi < 2; mi++) {
        int R = wm * 32 + mi * 16 + g;
#pragma unroll
        for (int ni = 0; ni < 4; ni++) {
            int col = wn * 32 + ni * 8 + 2 * t;
            sC[R * SCP + col]           = acc[mi][ni][0];
            sC[R * SCP + col + 1]       = acc[mi][ni][1];
            sC[(R + 8) * SCP + col]     = acc[mi][ni][2];
            sC[(R + 8) * SCP + col + 1] = acc[mi][ni][3];
        }
    }
    __syncthreads();

    for (int i = 0; i < 8; i++) {
        int m = warp * 8 + i;
        float4 v = *(float4*)&sC[m * SCP + 4 * lane];
        v.x += 0.01f; v.y += 0.01f; v.z += 0.01f; v.w += 0.01f;
        float s = v.x + v.y + v.z + v.w;
#pragma unroll
        for (int o = 16; o; o >>= 1) s += __shfl_xor_sync(0xFFFFFFFFu, s, o);
        float mu = s * (1.0f / HH);
        float dx = v.x - mu, dy = v.y - mu, dz = v.z - mu, dw = v.w - mu;
        float q = dx * dx + dy * dy + dz * dz + dw * dw;
#pragma unroll
        for (int o = 16; o; o >>= 1) q += __shfl_xor_sync(0xFFFFFFFFu, q, o);
        float rs = rsqrtf(q * (1.0f / HH) + 1e-5f);
        float4 o4;
        o4.x = fmaxf(dx * rs, 0.f);
        o4.y = fmaxf(dy * rs, 0.f);
        o4.z = fmaxf(dz * rs, 0.f);
        o4.w = fmaxf(dw * rs, 0.f);
        float4 h4 = ((const float4*)(g_h + (size_t)(m0 + m) * HH))[lane];
        o4.x += h4.x; o4.y += h4.y; o4.z += h4.z; o4.w += h4.w;
        size_t rowo = (size_t)(m0 + m) * HH;
        ((float4*)(g_probe + rowo))[lane] = o4;
        uint2 hpk;
        *(__half2*)&hpk.x = __floats2half2_rn(o4.x, o4.y);
        *(__half2*)&hpk.y = __floats2half2_rn(o4.z, o4.w);
        ((uint2*)(g_probe_hh + rowo))[lane] = hpk;
    }
}

// ---------------- prefix scan over node degrees ----------------
__global__ void k_ps1() {
    __shared__ int sh[256];
    int i = blockIdx.x * 256 + threadIdx.x;
    int v = g_deg[i];
    sh[threadIdx.x] = v;
    __syncthreads();
#pragma unroll
    for (int o = 1; o < 256; o <<= 1) {
        int t = (threadIdx.x >= o) ? sh[threadIdx.x - o] : 0;
        __syncthreads();
        sh[threadIdx.x] += t;
        __syncthreads();
    }
    g_row[i] = sh[threadIdx.x] - v;
    if (threadIdx.x == 255) g_bsum[blockIdx.x] = sh[255];
}

__global__ void k_ps2() {
    __shared__ int sh[512];
    int v = g_bsum[threadIdx.x];
    sh[threadIdx.x] = v;
    __syncthreads();
#pragma unroll
    for (int o = 1; o < 512; o <<= 1) {
        int t = (threadIdx.x >= o) ? sh[threadIdx.x - o] : 0;
        __syncthreads();
        sh[threadIdx.x] += t;
        __syncthreads();
    }
    g_bsum[threadIdx.x] = sh[threadIdx.x] - v;
}

__global__ void k_ps3() {
    int i = blockIdx.x * 256 + threadIdx.x;
    int r = g_row[i] + g_bsum[i >> 8];
    g_row[i] = r;
    g_cursor[i] = r;
    if (i == 0) g_row[NN] = EE;
}

// ---------------- CSR scatter (re-decodes raw edges) ----------------
__global__ void k_csr_scatter(const void* __restrict__ ei_raw, const void* __restrict__ et_raw) {
    int e = blockIdx.x * blockDim.x + threadIdx.x;
    if (e >= EE) return;
    int s, d, t;
    if (g_is64) {
        const long long* ei = (const long long*)ei_raw;
        const long long* et = (const long long*)et_raw;
        s = (int)ei[e];
        d = (int)ei[(size_t)EE + e];
        t = (int)et[e];
    } else {
        const int* ei = (const int*)ei_raw;
        const int* et = (const int*)et_raw;
        s = ei[e];
        d = ei[EE + e];
        t = et[e];
    }
    int pos = atomicAdd(&g_cursor[d], 1);
    float inv = 1.0f / fmaxf(g_cnt[d * RR + t], 1.0f);
    g_meta[pos] = make_int2(s | (t << 20), __float_as_int(inv));
}

// ---------------- weight preconvert ----------------
__global__ void k_wconv(const float* __restrict__ basis, const float* __restrict__ root) {
    int idx = blockIdx.x * blockDim.x + threadIdx.x;
    if (idx >= LL * NC16 * 128 * 16) return;
    int l   = idx / (NC16 * 128 * 16);
    int rem = idx % (NC16 * 128 * 16);
    int kc  = rem >> 11;
    int n   = (rem >> 4) & 127;
    int kr  = rem & 15;
    int kg  = kc * 16 + kr;
    float v = (kg < 512) ? basis[(size_t)l * 512 * HH + (size_t)kg * HH + n]
                         : root [(size_t)l * HH * HH + (size_t)(kg - 512) * HH + n];
    g_wB[idx] = __float2half_rn(v);
}

// ---------------- input projection ----------------
__global__ void k_inproj(const float* __restrict__ x, const float* __restrict__ W,
                         const float* __restrict__ b) {
    __shared__ float Ws[FF * HH];
    __shared__ float xs[8][FF];
    int tid = threadIdx.x;
    for (int i = tid; i < FF * HH; i += 128) Ws[i] = W[i];
    int n0 = blockIdx.x * 8;
    for (int i = tid; i < 8 * FF; i += 128) xs[i / FF][i % FF] = x[(size_t)n0 * FF + i];
    __syncthreads();
    float bj = b[tid];
#pragma unroll
    for (int u = 0; u < 8; u++) {
        float acc = bj;
#pragma unroll
        for (int k = 0; k < FF; k++) acc += xs[u][k] * Ws[k * HH + tid];
        g_h  [(size_t)(n0 + u) * HH + tid] = acc;
        g_hh0[(size_t)(n0 + u) * HH + tid] = __float2half_rn(acc);
    }
}

// ================= fused RGCN layer =================
__global__ void __launch_bounds__(256, 2) k_layer(
    const float* __restrict__ in, float* __restrict__ out,
    const __half* __restrict__ hh_in, __half* __restrict__ hh_out,
    const __half* __restrict__ wB_l,
    const float* __restrict__ comp_l, const float* __restrict__ bias_l,
    const float* __restrict__ gam, const float* __restrict__ bet, int residual)
{
    extern __shared__ __align__(16) char dyn[];
    __half* sA = (__half*)dyn;
    __half* sB = (__half*)(dyn + TM * SAP * 2);
    float*  sC = (float*)dyn;
    __shared__ float s_comp[RR * BB];

    int tid = threadIdx.x, warp = tid >> 5, lane = tid & 31;
    int m0 = blockIdx.x * TM;
    if (tid < RR * BB) s_comp[tid] = comp_l[tid];

    uint32_t smem_u32;
    asm("{ .reg .u64 t; cvta.to.shared.u64 t, %1; cvt.u32.u64 %0, t; }"
        : "=r"(smem_u32) : "l"(dyn));
    uint32_t sB32 = smem_u32 + TM * SAP * 2;

    int nB = tid >> 1, hp = tid & 1;
    uint32_t dst_off = (uint32_t)(nB * SBP + hp * 8) * 2;
#pragma unroll
    for (int c = 0; c < 4; c++) {
        cp16(sB32 + c * SB_BUF * 2 + dst_off,
             wB_l + ((size_t)c * 128 + nB) * 16 + hp * 8);
        CP_COMMIT();
    }

    for (int i = tid; i < TM * 16; i += 256) {
        int m = i >> 4, c8 = i & 15;
        *(uint4*)(sA + m * SAP + 512 + c8 * 8) =
            ((const uint4*)(hh_in + (size_t)(m0 + m) * HH))[c8];
    }
    __syncthreads();

#define ACC_EDGE(mt, r)                                                       \
    {                                                                         \
        int   t_  = mt.x >> 20;                                               \
        float iv_ = __int_as_float(mt.y);                                     \
        float c0 = s_comp[t_ * BB + 0] * iv_;                                 \
        float c1 = s_comp[t_ * BB + 1] * iv_;                                 \
        float c2 = s_comp[t_ * BB + 2] * iv_;                                 \
        float c3 = s_comp[t_ * BB + 3] * iv_;                                 \
        float2 p0 = __half22float2(*(__half2*)&r.x);                          \
        float2 p1 = __half22float2(*(__half2*)&r.y);                          \
        a0.x += c0 * p0.x; a0.y += c0 * p0.y; a0.z += c0 * p1.x; a0.w += c0 * p1.y; \
        a1.x += c1 * p0.x; a1.y += c1 * p0.y; a1.z += c1 * p1.x; a1.w += c1 * p1.y; \
        a2.x += c2 * p0.x; a2.y += c2 * p0.y; a2.z += c2 * p1.x; a2.w += c2 * p1.y; \
        a3.x += c3 * p0.x; a3.y += c3 * p0.y; a3.z += c3 * p1.x; a3.w += c3 * p1.y; \
    }

    for (int ii = 0; ii < 8; ii++) {
        int m = warp * 8 + ii;
        int node = m0 + m;
        int beg = g_row[node], end = g_row[node + 1];
        float4 a0 = make_float4(0.f, 0.f, 0.f, 0.f);
        float4 a1 = a0, a2 = a0, a3 = a0;
        int e = beg;
        for (; e + 4 <= end; e += 4) {
            int2 m0_ = __ldg(&g_meta[e + 0]);
            int2 m1_ = __ldg(&g_meta[e + 1]);
            int2 m2_ = __ldg(&g_meta[e + 2]);
            int2 m3_ = __ldg(&g_meta[e + 3]);
            uint2 r0 = __ldg((const uint2*)(hh_in + (size_t)(m0_.x & 0xFFFFF) * HH) + lane);
            uint2 r1 = __ldg((const uint2*)(hh_in + (size_t)(m1_.x & 0xFFFFF) * HH) + lane);
            uint2 r2 = __ldg((const uint2*)(hh_in + (size_t)(m2_.x & 0xFFFFF) * HH) + lane);
            uint2 r3 = __ldg((const uint2*)(hh_in + (size_t)(m3_.x & 0xFFFFF) * HH) + lane);
            ACC_EDGE(m0_, r0);
            ACC_EDGE(m1_, r1);
            ACC_EDGE(m2_, r2);
            ACC_EDGE(m3_, r3);
        }
        for (; e < end; e++) {
            int2 mt = __ldg(&g_meta[e]);
            uint2 rr = __ldg((const uint2*)(hh_in + (size_t)(mt.x & 0xFFFFF) * HH) + lane);
            ACC_EDGE(mt, rr);
        }
        __half* dst = sA + m * SAP + 4 * lane;
        *(__half2*)(dst + 0 * 128 + 0) = __floats2half2_rn(a0.x, a0.y);
        *(__half2*)(dst + 0 * 128 + 2) = __floats2half2_rn(a0.z, a0.w);
        *(__half2*)(dst + 1 * 128 + 0) = __floats2half2_rn(a1.x, a1.y);
        *(__half2*)(dst + 1 * 128 + 2) = __floats2half2_rn(a1.z, a1.w);
        *(__half2*)(dst + 2 * 128 + 0) = __floats2half2_rn(a2.x, a2.y);
        *(__half2*)(dst + 2 * 128 + 2) = __floats2half2_rn(a2.z, a2.w);
        *(__half2*)(dst + 3 * 128 + 0) = __floats2half2_rn(a3.x, a3.y);
        *(__half2*)(dst + 3 * 128 + 2) = __floats2half2_rn(a3.z, a3.w);
    }
#undef ACC_EDGE
    __syncthreads();

    int wm = warp & 1, wn = warp >> 1;
    int g = lane >> 2, t = lane & 3;
    float acc[2][4][4];
#pragma unroll
    for (int i = 0; i < 2; i++)
#pragma unroll
        for (int j = 0; j < 4; j++)
#pragma unroll
            for (int c = 0; c < 4; c++) acc[i][j][c] = 0.f;

    int bufr = 0;
    for (int kc = 0; kc < NC16; kc++) {
        CP_WAIT3();
        __syncthreads();
        int bufw = bufr + 4; if (bufw >= NBUF) bufw -= NBUF;
        if (kc + 4 < NC16)
            cp16(sB32 + bufw * SB_BUF * 2 + dst_off,
                 wB_l + ((size_t)(kc + 4) * 128 + nB) * 16 + hp * 8);
        CP_COMMIT();

        const __half* bb = sB + bufr * SB_BUF;
        int ka = kc * 16 + 2 * t;
        uint32_t Bf[4][2];
#pragma unroll
        for (int ni = 0; ni < 4; ni++) {
            int n = wn * 32 + ni * 8 + g;
            Bf[ni][0] = *(const uint32_t*)&bb[n * SBP + 2 * t];
            Bf[ni][1] = *(const uint32_t*)&bb[n * SBP + 2 * t + 8];
        }
#pragma unroll
        for (int mi = 0; mi < 2; mi++) {
            int R = wm * 32 + mi * 16 + g;
            uint32_t A0 = *(const uint32_t*)&sA[R * SAP + ka];
            uint32_t A1 = *(const uint32_t*)&sA[(R + 8) * SAP + ka];
            uint32_t A2 = *(const uint32_t*)&sA[R * SAP + ka + 8];
            uint32_t A3 = *(const uint32_t*)&sA[(R + 8) * SAP + ka + 8];
#pragma unroll
            for (int ni = 0; ni < 4; ni++)
                mma_f16(acc[mi][ni], A0, A1, A2, A3, Bf[ni][0], Bf[ni][1]);
        }
        bufr++; if (bufr == NBUF) bufr = 0;
    }
    __syncthreads();

#pragma unroll
    for (int mi = 0; mi < 2; mi++) {
        int R = wm * 32 + mi * 16 + g;
#pragma unroll
        for (int ni = 0; ni < 4; ni++) {
            int col = wn * 32 + ni * 8 + 2 * t;
            sC[R * SCP + col]           = acc[mi][ni][0];
            sC[R * SCP + col + 1]       = acc[mi][ni][1];
            sC[(R + 8) * SCP + col]     = acc[mi][ni][2];
            sC[(R + 8) * SCP + col + 1] = acc[mi][ni][3];
        }
    }
    __syncthreads();

    for (int i = 0; i < 8; i++) {
        int m = warp * 8 + i;
        float4 v = *(float4*)&sC[m * SCP + 4 * lane];
        float4 bi = __ldg(&((const float4*)bias_l)[lane]);
        v.x += bi.x; v.y += bi.y; v.z += bi.z; v.w += bi.w;
        float s = v.x + v.y + v.z + v.w;
#pragma unroll
        for (int o = 16; o; o >>= 1) s += __shfl_xor_sync(0xFFFFFFFFu, s, o);
        float mu = s * (1.0f / HH);
        float dx = v.x - mu, dy = v.y - mu, dz = v.z - mu, dw = v.w - mu;
        float q = dx * dx + dy * dy + dz * dz + dw * dw;
#pragma unroll
        for (int o = 16; o; o >>= 1) q += __shfl_xor_sync(0xFFFFFFFFu, q, o);
        float rs = rsqrtf(q * (1.0f / HH) + 1e-5f);
        float4 g4 = __ldg(&((const float4*)gam)[lane]);
        float4 b4 = __ldg(&((const float4*)bet)[lane]);
        float4 o4;
        o4.x = fmaxf(dx * rs * g4.x + b4.x, 0.f);
        o4.y = fmaxf(dy * rs * g4.y + b4.y, 0.f);
        o4.z = fmaxf(dz * rs * g4.z + b4.z, 0.f);
        o4.w = fmaxf(dw * rs * g4.w + b4.w, 0.f);
        if (residual) {
            float4 h4 = ((const float4*)(in + (size_t)(m0 + m) * HH))[lane];
            o4.x += h4.x; o4.y += h4.y; o4.z += h4.z; o4.w += h4.w;
        }
        size_t rowo = (size_t)(m0 + m) * HH;
        ((float4*)(out + rowo))[lane] = o4;
        uint2 hpk;
        *(__half2*)&hpk.x = __floats2half2_rn(o4.x, o4.y);
        *(__half2*)&hpk.y = __floats2half2_rn(o4.z, o4.w);
        ((uint2*)(hh_out + rowo))[lane] = hpk;
    }
}

// ---------------- head ----------------
#define KC   16
#define LDSA 136
__global__ void __launch_bounds__(256) k_head(
    const float* __restrict__ A1,
    const float* __restrict__ W1, const float* __restrict__ b1,
    const float* __restrict__ W2, const float* __restrict__ b2,
    float* __restrict__ outp)
{
    extern __shared__ __align__(16) float sU[];
    __shared__ float sW2[HH * OUTD];
    __shared__ float sb2[OUTD];
    float (*Ah)[LDSA] = (float(*)[LDSA])sU;
    float (*Al)[LDSA] = (float(*)[LDSA])(sU + KC * LDSA);
    float (*Bh)[LDSA] = (float(*)[LDSA])(sU + 2 * KC * LDSA);
    float (*Bl)[LDSA] = (float(*)[LDSA])(sU + 3 * KC * LDSA);
    float* sC = sU;

    int tid  = threadIdx.x;
    int warp = tid >> 5, lane = tid & 31;
    int wm = warp & 1, wn = warp >> 1;
    int g  = lane >> 2, t = lane & 3;
    int m0 = blockIdx.x * 128;

    for (int i = tid; i < HH * OUTD; i += 256) sW2[i] = W2[i];
    if (tid < OUTD) sb2[tid] = b2[tid];

    float acc[4][4][4];
#pragma unroll
    for (int i = 0; i < 4; i++)
#pragma unroll
        for (int j = 0; j < 4; j++)
#pragma unroll
            for (int c = 0; c < 4; c++) acc[i][j][c] = 0.f;

    for (int kk = 0; kk < HH; kk += KC) {
        {
            int m   = tid >> 1;
            int kq0 = (tid & 1) * 8;
#pragma unroll
            for (int q = 0; q < 2; q++) {
                float4 v = *(const float4*)(A1 + (size_t)(m0 + m) * HH + kk + kq0 + q * 4);
                float e[4] = {v.x, v.y, v.z, v.w};
#pragma unroll
                for (int u = 0; u < 4; u++) {
                    float hi = tf32r(e[u]);
                    Ah[kq0 + q * 4 + u][m] = hi;
                    Al[kq0 + q * 4 + u][m] = tf32r(e[u] - hi);
                }
            }
        }
        {
            const float* Bp = W1 + (size_t)kk * HH;
            int kr  = tid >> 4;
            int cc0 = (tid & 15) * 8;
#pragma unroll
            for (int q = 0; q < 2; q++) {
                float4 v = *(const float4*)(Bp + (size_t)kr * HH + cc0 + q * 4);
                float e[4] = {v.x, v.y, v.z, v.w};
#pragma unroll
                for (int u = 0; u < 4; u++) {
                    float hi = tf32r(e[u]);
                    Bh[kr][cc0 + q * 4 + u] = hi;
                    Bl[kr][cc0 + q * 4 + u] = tf32r(e[u] - hi);
                }
            }
        }
        __syncthreads();

#pragma unroll
        for (int ks = 0; ks < KC / 8; ks++) {
            int k0 = ks * 8;
            uint32_t bh[4][2], bl[4][2];
#pragma unroll
            for (int ni = 0; ni < 4; ni++) {
                int nb = wn * 32 + ni * 8 + g;
                bh[ni][0] = __float_as_uint(Bh[k0 + t    ][nb]);
                bh[ni][1] = __float_as_uint(Bh[k0 + t + 4][nb]);
                bl[ni][0] = __float_as_uint(Bl[k0 + t    ][nb]);
                bl[ni][1] = __float_as_uint(Bl[k0 + t + 4][nb]);
            }
#pragma unroll
            for (int mi = 0; mi < 4; mi++) {
                int R = wm * 64 + mi * 16 + g;
                uint32_t ah0 = __float_as_uint(Ah[k0 + t    ][R]);
                uint32_t ah1 = __float_as_uint(Ah[k0 + t    ][R + 8]);
                uint32_t ah2 = __float_as_uint(Ah[k0 + t + 4][R]);
                uint32_t ah3 = __float_as_uint(Ah[k0 + t + 4][R + 8]);
                uint32_t al0 = __float_as_uint(Al[k0 + t    ][R]);
                uint32_t al1 = __float_as_uint(Al[k0 + t    ][R + 8]);
                uint32_t al2 = __float_as_uint(Al[k0 + t + 4][R]);
                uint32_t al3 = __float_as_uint(Al[k0 + t + 4][R + 8]);
#pragma unroll
                for (int ni = 0; ni < 4; ni++) {
                    float* c = acc[mi][ni];
                    mma_tf32(c[0], c[1], c[2], c[3], ah0, ah1, ah2, ah3, bh[ni][0], bh[ni][1]);
                    mma_tf32(c[0], c[1], c[2], c[3], ah0, ah1, ah2, ah3, bl[ni][0], bl[ni][1]);
                    mma_tf32(c[0], c[1], c[2], c[3], al0, al1, al2, al3, bh[ni][0], bh[ni][1]);
                }
            }
        }
        __syncthreads();
    }

#pragma unroll
    for (int ni = 0; ni < 4; ni++) {
        int col = wn * 32 + ni * 8 + 2 * t;
        float b0 = b1[col], bb1 = b1[col + 1];
#pragma unroll
        for (int mi = 0; mi < 4; mi++) {
            int R = wm * 64 + mi * 16 + g;
            float* c = acc[mi][ni];
            sC[R * SCP + col]           = fmaxf(c[0] + b0, 0.f);
            sC[R * SCP + col + 1]       = fmaxf(c[1] + bb1, 0.f);
            sC[(R + 8) * SCP + col]     = fmaxf(c[2] + b0, 0.f);
            sC[(R + 8) * SCP + col + 1] = fmaxf(c[3] + bb1, 0.f);
        }
    }
    __syncthreads();

    {
        int row = tid >> 1;
        int cb  = (tid & 1) * 4;
        float o0 = sb2[cb], o1 = sb2[cb + 1], o2 = sb2[cb + 2], o3 = sb2[cb + 3];
#pragma unroll 4
        for (int k = 0; k < HH; k++) {
            float hv = sC[row * SCP + k];
            float4 w = *(const float4*)&sW2[k * OUTD + cb];
            o0 += hv * w.x; o1 += hv * w.y; o2 += hv * w.z; o3 += hv * w.w;
        }
        *(float4*)(outp + (size_t)(m0 + row) * OUTD + cb) = make_float4(o0, o1, o2, o3);
    }
}

// ---------------- launch ----------------
extern "C" void kernel_launch(void* const* d_in, const int* in_sizes, int n_in,
                              void* d_out, int out_size) {
    const float* x     = (const float*)d_in[0];
    const void*  ei    = d_in[1];
    const void*  et    = d_in[2];
    const float* W_in  = (const float*)d_in[3];
    const float* b_in  = (const float*)d_in[4];
    const float* basis = (const float*)d_in[5];
    const float* comp  = (const float*)d_in[6];
    const float* root  = (const float*)d_in[7];
    const float* bias  = (const float*)d_in[8];
    const float* ln_g  = (const float*)d_in[9];
    const float* ln_b  = (const float*)d_in[10];
    const float* W1    = (const float*)d_in[11];
    const float* b1    = (const float*)d_in[12];
    const float* W2    = (const float*)d_in[13];
    const float* b2    = (const float*)d_in[14];

    void *p_h, *p_t, *p_hh0, *p_hh1, *p_wB;
    cudaGetSymbolAddress(&p_h,   g_h);
    cudaGetSymbolAddress(&p_t,   g_t);
    cudaGetSymbolAddress(&p_hh0, g_hh0);
    cudaGetSymbolAddress(&p_hh1, g_hh1);
    cudaGetSymbolAddress(&p_wB,  g_wB);
    cudaFuncSetAttribute(k_layer, cudaFuncAttributeMaxDynamicSharedMemorySize, SMEM_LAYER);
    cudaFuncSetAttribute(k_probe, cudaFuncAttributeMaxDynamicSharedMemorySize, SMEM_LAYER);
    cudaFuncSetAttribute(k_head,  cudaFuncAttributeMaxDynamicSharedMemorySize, SMEM_HEAD);

    // ---- preprocessing; k_probe is the 4th launch (ncu capture slot) ----
    k_detect<<<1, 256>>>((const int*)ei);
    k_zero_cnt<<<(NN * RR + 255) / 256, 256>>>();
    k_prep_count<<<EE / 256, 256>>>(ei, et);
    k_probe<<<PROBE_BLOCKS, 256, SMEM_LAYER>>>();        // profiling probe
    k_ps1<<<NN / 256, 256>>>();
    k_ps2<<<1, 512>>>();
    k_ps3<<<NN / 256, 256>>>();
    k_csr_scatter<<<EE / 256, 256>>>(ei, et);
    k_wconv<<<(LL * NC16 * 128 * 16 + 255) / 256, 256>>>(basis, root);
    k_inproj<<<NN / 8, 128>>>(x, W_in, b_in);

    // ---- fused layers ----
    float*  bufs[2] = {(float*)p_h, (float*)p_t};
    __half* hhb[2]  = {(__half*)p_hh0, (__half*)p_hh1};
    for (int i = 0; i < LL; i++) {
        k_layer<<<NN / TM, 256, SMEM_LAYER>>>(
            bufs[i & 1], bufs[(i + 1) & 1],
            hhb[i & 1], hhb[(i + 1) & 1],
            (const __half*)p_wB + (size_t)i * NC16 * 128 * 16,
            comp + i * RR * BB,
            bias + i * HH, ln_g + i * HH, ln_b + i * HH, i > 0 ? 1 : 0);
    }

    // ---- fused head ----
    k_head<<<NN / 128, 256, SMEM_HEAD>>>(bufs[LL & 1], W1, b1, W2, b2, (float*)d_out);
}

// round 13
// speedup vs baseline: 1.2561x; 1.2561x over previous
#include <cuda_runtime.h>
#include <cuda_fp16.h>
#include <cstdint>

#define NN   131072
#define EE   2097152
#define FF   32
#define HH   128
#define RR   10
#define BB   4
#define LL   3
#define OUTD 8

#define TM   32               // layer-kernel block rows (dst nodes)
#define SAP  648              // sA k-stride in halves (640 + 8 pad)
#define SBP  24               // sB row stride in halves (16 used + 8 pad)
#define SB_BUF (128 * SBP)    // halves per 16-k B buffer (3072)
#define SCP  132              // sC row stride in floats
#define NC16 40               // 16-wide K chunks (640 total)
#define SMEM_LAYER (TM * SAP * 2 + 2 * SB_BUF * 2)   // 41472 + 12288 = 53760 B
#define SMEM_HEAD  (128 * SCP * 4)                   // 67584 B

// ---------------- device scratch ----------------
__device__ float  g_h  [(size_t)NN * HH];
__device__ float  g_t  [(size_t)NN * HH];
__device__ __half g_hh0[(size_t)NN * HH];   // fp16 mirror (ping)
__device__ __half g_hh1[(size_t)NN * HH];   // fp16 mirror (pong)
__device__ __half g_wB [(size_t)LL * NC16 * 128 * 16]; // staged fp16 weights
__device__ float  g_cnt[NN * RR];
__device__ int    g_deg[NN];
__device__ int    g_row[NN + 1];
__device__ int    g_bsum[512];
__device__ int    g_cursor[NN];
__device__ int2   g_meta[EE];          // dst-sorted {src|rel<<20, bits(1/cnt)}
__device__ int    g_is64;

// ---------------- helpers ----------------
__device__ __forceinline__ float tf32r(float x) {
    uint32_t o;
    asm("cvt.rna.tf32.f32 %0, %1;" : "=r"(o) : "f"(x));
    return __uint_as_float(o);
}

__device__ __forceinline__ void mma_tf32(float& c0, float& c1, float& c2, float& c3,
                                         uint32_t a0, uint32_t a1, uint32_t a2, uint32_t a3,
                                         uint32_t b0, uint32_t b1) {
    asm volatile(
        "mma.sync.aligned.m16n8k8.row.col.f32.tf32.tf32.f32 "
        "{%0,%1,%2,%3}, {%4,%5,%6,%7}, {%8,%9}, {%0,%1,%2,%3};"
        : "+f"(c0), "+f"(c1), "+f"(c2), "+f"(c3)
        : "r"(a0), "r"(a1), "r"(a2), "r"(a3), "r"(b0), "r"(b1));
}

__device__ __forceinline__ void mma_f16(float* c,
                                        uint32_t a0, uint32_t a1, uint32_t a2, uint32_t a3,
                                        uint32_t b0, uint32_t b1) {
    asm volatile(
        "mma.sync.aligned.m16n8k16.row.col.f32.f16.f16.f32 "
        "{%0,%1,%2,%3}, {%4,%5,%6,%7}, {%8,%9}, {%0,%1,%2,%3};"
        : "+f"(c[0]), "+f"(c[1]), "+f"(c[2]), "+f"(c[3])
        : "r"(a0), "r"(a1), "r"(a2), "r"(a3), "r"(b0), "r"(b1));
}

// ---------------- dtype detect ----------------
__global__ void k_detect(const int* __restrict__ ei) {
    __shared__ int cnt;
    if (threadIdx.x == 0) cnt = 0;
    __syncthreads();
    if (ei[threadIdx.x * 2 + 1] != 0) atomicAdd(&cnt, 1);
    __syncthreads();
    if (threadIdx.x == 0) g_is64 = (cnt == 0) ? 1 : 0;
}

__global__ void k_zero_cnt() {
    int i = blockIdx.x * blockDim.x + threadIdx.x;
    if (i < NN * RR) g_cnt[i] = 0.0f;
    if (i < NN) g_deg[i] = 0;
}

// ---------------- decode + count ----------------
__global__ void k_prep_count(const void* __restrict__ ei_raw, const void* __restrict__ et_raw) {
    int e = blockIdx.x * blockDim.x + threadIdx.x;
    if (e >= EE) return;
    int d, t;
    if (g_is64) {
        const long long* ei = (const long long*)ei_raw;
        const long long* et = (const long long*)et_raw;
        d = (int)ei[(size_t)EE + e];
        t = (int)et[e];
    } else {
        const int* ei = (const int*)ei_raw;
        const int* et = (const int*)et_raw;
        d = ei[EE + e];
        t = et[e];
    }
    atomicAdd(&g_cnt[d * RR + t], 1.0f);
    atomicAdd(&g_deg[d], 1);
}

// ---------------- prefix scan over node degrees ----------------
__global__ void k_ps1() {
    __shared__ int sh[256];
    int i = blockIdx.x * 256 + threadIdx.x;
    int v = g_deg[i];
    sh[threadIdx.x] = v;
    __syncthreads();
#pragma unroll
    for (int o = 1; o < 256; o <<= 1) {
        int t = (threadIdx.x >= o) ? sh[threadIdx.x - o] : 0;
        __syncthreads();
        sh[threadIdx.x] += t;
        __syncthreads();
    }
    g_row[i] = sh[threadIdx.x] - v;
    if (threadIdx.x == 255) g_bsum[blockIdx.x] = sh[255];
}

__global__ void k_ps2() {
    __shared__ int sh[512];
    int v = g_bsum[threadIdx.x];
    sh[threadIdx.x] = v;
    __syncthreads();
#pragma unroll
    for (int o = 1; o < 512; o <<= 1) {
        int t = (threadIdx.x >= o) ? sh[threadIdx.x - o] : 0;
        __syncthreads();
        sh[threadIdx.x] += t;
        __syncthreads();
    }
    g_bsum[threadIdx.x] = sh[threadIdx.x] - v;
}

__global__ void k_ps3() {
    int i = blockIdx.x * 256 + threadIdx.x;
    int r = g_row[i] + g_bsum[i >> 8];
    g_row[i] = r;
    g_cursor[i] = r;
    if (i == 0) g_row[NN] = EE;
}

// ---------------- CSR scatter (re-decodes raw edges) ----------------
__global__ void k_csr_scatter(const void* __restrict__ ei_raw, const void* __restrict__ et_raw) {
    int e = blockIdx.x * blockDim.x + threadIdx.x;
    if (e >= EE) return;
    int s, d, t;
    if (g_is64) {
        const long long* ei = (const long long*)ei_raw;
        const long long* et = (const long long*)et_raw;
        s = (int)ei[e];
        d = (int)ei[(size_t)EE + e];
        t = (int)et[e];
    } else {
        const int* ei = (const int*)ei_raw;
        const int* et = (const int*)et_raw;
        s = ei[e];
        d = ei[EE + e];
        t = et[e];
    }
    int pos = atomicAdd(&g_cursor[d], 1);
    float inv = 1.0f / fmaxf(g_cnt[d * RR + t], 1.0f);
    g_meta[pos] = make_int2(s | (t << 20), __float_as_int(inv));
}

// ---------------- weight preconvert: basis||root -> staged fp16 [NC16][128][16] ----------------
__global__ void k_wconv(const float* __restrict__ basis, const float* __restrict__ root) {
    int idx = blockIdx.x * blockDim.x + threadIdx.x;
    if (idx >= LL * NC16 * 128 * 16) return;
    int l   = idx / (NC16 * 128 * 16);
    int rem = idx % (NC16 * 128 * 16);
    int kc  = rem >> 11;
    int n   = (rem >> 4) & 127;
    int kr  = rem & 15;
    int kg  = kc * 16 + kr;
    float v = (kg < 512) ? basis[(size_t)l * 512 * HH + (size_t)kg * HH + n]
                         : root [(size_t)l * HH * HH + (size_t)(kg - 512) * HH + n];
    g_wB[idx] = __float2half_rn(v);
}

// ---------------- input projection (writes fp32 + fp16 mirror) ----------------
__global__ void k_inproj(const float* __restrict__ x, const float* __restrict__ W,
                         const float* __restrict__ b) {
    __shared__ float Ws[FF * HH];
    __shared__ float xs[8][FF];
    int tid = threadIdx.x;
    for (int i = tid; i < FF * HH; i += 128) Ws[i] = W[i];
    int n0 = blockIdx.x * 8;
    for (int i = tid; i < 8 * FF; i += 128) xs[i / FF][i % FF] = x[(size_t)n0 * FF + i];
    __syncthreads();
    float bj = b[tid];
#pragma unroll
    for (int u = 0; u < 8; u++) {
        float acc = bj;
#pragma unroll
        for (int k = 0; k < FF; k++) acc += xs[u][k] * Ws[k * HH + tid];
        g_h  [(size_t)(n0 + u) * HH + tid] = acc;
        g_hh0[(size_t)(n0 + u) * HH + tid] = __float2half_rn(acc);
    }
}

// ================= fused RGCN layer (TM=32, 4 blocks/SM) =================
__global__ void __launch_bounds__(256, 4) k_layer(
    const float* __restrict__ in, float* __restrict__ out,
    const __half* __restrict__ hh_in, __half* __restrict__ hh_out,
    const __half* __restrict__ wB_l,
    const float* __restrict__ comp_l, const float* __restrict__ bias_l,
    const float* __restrict__ gam, const float* __restrict__ bet, int residual)
{
    extern __shared__ __align__(16) char dyn[];
    __half* sA = (__half*)dyn;                       // [TM][SAP]
    __half* sB = (__half*)(dyn + TM * SAP * 2);      // 2 x [128][SBP]
    float*  sC = (float*)dyn;                        // epilogue reuse [TM][SCP]
    __shared__ float s_comp[RR * BB];

    int tid = threadIdx.x, warp = tid >> 5, lane = tid & 31;
    int m0 = blockIdx.x * TM;
    if (tid < RR * BB) s_comp[tid] = comp_l[tid];

    // ---- stage h (root planes 512..639) from fp16 mirror ----
    for (int i = tid; i < TM * 16; i += 256) {
        int m = i >> 4, c8 = i & 15;
        *(uint4*)(sA + m * SAP + 512 + c8 * 8) =
            ((const uint4*)(hh_in + (size_t)(m0 + m) * HH))[c8];
    }

    // ---- prologue: stage B chunk 0 into buf 0 ----
    int nB = tid >> 1, hp = tid & 1;
    {
        uint4 p0 = ((const uint4*)wB_l)[(size_t)(0 * 128 + nB) * 2 + hp];
        *(uint4*)(sB + 0 * SB_BUF + nB * SBP + hp * 8) = p0;
    }
    __syncthreads();

    // ---- aggregation: 4 nodes per warp, fp32 accumulators, 4-way unrolled ----
#define ACC_EDGE(mt, r)                                                       \
    {                                                                         \
        int   t_  = mt.x >> 20;                                               \
        float iv_ = __int_as_float(mt.y);                                     \
        float c0 = s_comp[t_ * BB + 0] * iv_;                                 \
        float c1 = s_comp[t_ * BB + 1] * iv_;                                 \
        float c2 = s_comp[t_ * BB + 2] * iv_;                                 \
        float c3 = s_comp[t_ * BB + 3] * iv_;                                 \
        float2 p0 = __half22float2(*(__half2*)&r.x);                          \
        float2 p1 = __half22float2(*(__half2*)&r.y);                          \
        a0.x += c0 * p0.x; a0.y += c0 * p0.y; a0.z += c0 * p1.x; a0.w += c0 * p1.y; \
        a1.x += c1 * p0.x; a1.y += c1 * p0.y; a1.z += c1 * p1.x; a1.w += c1 * p1.y; \
        a2.x += c2 * p0.x; a2.y += c2 * p0.y; a2.z += c2 * p1.x; a2.w += c2 * p1.y; \
        a3.x += c3 * p0.x; a3.y += c3 * p0.y; a3.z += c3 * p1.x; a3.w += c3 * p1.y; \
    }

    for (int ii = 0; ii < 4; ii++) {
        int m = warp * 4 + ii;
        int node = m0 + m;
        int beg = g_row[node], end = g_row[node + 1];
        float4 a0 = make_float4(0.f, 0.f, 0.f, 0.f);
        float4 a1 = a0, a2 = a0, a3 = a0;
        int e = beg;
        for (; e + 4 <= end; e += 4) {
            int2 m0_ = __ldg(&g_meta[e + 0]);
            int2 m1_ = __ldg(&g_meta[e + 1]);
            int2 m2_ = __ldg(&g_meta[e + 2]);
            int2 m3_ = __ldg(&g_meta[e + 3]);
            uint2 r0 = __ldg((const uint2*)(hh_in + (size_t)(m0_.x & 0xFFFFF) * HH) + lane);
            uint2 r1 = __ldg((const uint2*)(hh_in + (size_t)(m1_.x & 0xFFFFF) * HH) + lane);
            uint2 r2 = __ldg((const uint2*)(hh_in + (size_t)(m2_.x & 0xFFFFF) * HH) + lane);
            uint2 r3 = __ldg((const uint2*)(hh_in + (size_t)(m3_.x & 0xFFFFF) * HH) + lane);
            ACC_EDGE(m0_, r0);
            ACC_EDGE(m1_, r1);
            ACC_EDGE(m2_, r2);
            ACC_EDGE(m3_, r3);
        }
        for (; e < end; e++) {
            int2 mt = __ldg(&g_meta[e]);
            uint2 rr = __ldg((const uint2*)(hh_in + (size_t)(mt.x & 0xFFFFF) * HH) + lane);
            ACC_EDGE(mt, rr);
        }
        __half* dst = sA + m * SAP + 4 * lane;
        *(__half2*)(dst + 0 * 128 + 0) = __floats2half2_rn(a0.x, a0.y);
        *(__half2*)(dst + 0 * 128 + 2) = __floats2half2_rn(a0.z, a0.w);
        *(__half2*)(dst + 1 * 128 + 0) = __floats2half2_rn(a1.x, a1.y);
        *(__half2*)(dst + 1 * 128 + 2) = __floats2half2_rn(a1.z, a1.w);
        *(__half2*)(dst + 2 * 128 + 0) = __floats2half2_rn(a2.x, a2.y);
        *(__half2*)(dst + 2 * 128 + 2) = __floats2half2_rn(a2.z, a2.w);
        *(__half2*)(dst + 3 * 128 + 0) = __floats2half2_rn(a3.x, a3.y);
        *(__half2*)(dst + 3 * 128 + 2) = __floats2half2_rn(a3.z, a3.w);
    }
#undef ACC_EDGE
    __syncthreads();

    // ---- GEMM: [TM x 640] @ [640 x 128], fp16 mma, 1m x 8n warp grid ----
    int wn = warp;                   // warp tile: 32 rows x 16 cols
    int g = lane >> 2, t = lane & 3;
    float acc[2][2][4];
#pragma unroll
    for (int i = 0; i < 2; i++)
#pragma unroll
        for (int j = 0; j < 2; j++)
#pragma unroll
            for (int c = 0; c < 4; c++) acc[i][j][c] = 0.f;

    uint4 pb;
    for (int kc = 0; kc < NC16; kc++) {
        if (kc < NC16 - 1)
            pb = ((const uint4*)wB_l)[(size_t)((kc + 1) * 128 + nB) * 2 + hp];
        const __half* bb = sB + (kc & 1) * SB_BUF;
        int ka = kc * 16 + 2 * t;
        uint32_t Bf[2][2];
#pragma unroll
        for (int ni = 0; ni < 2; ni++) {
            int n = wn * 16 + ni * 8 + g;
            Bf[ni][0] = *(const uint32_t*)&bb[n * SBP + 2 * t];
            Bf[ni][1] = *(const uint32_t*)&bb[n * SBP + 2 * t + 8];
        }
#pragma unroll
        for (int mi = 0; mi < 2; mi++) {
            int R = mi * 16 + g;
            uint32_t A0 = *(const uint32_t*)&sA[R * SAP + ka];
            uint32_t A1 = *(const uint32_t*)&sA[(R + 8) * SAP + ka];
            uint32_t A2 = *(const uint32_t*)&sA[R * SAP + ka + 8];
            uint32_t A3 = *(const uint32_t*)&sA[(R + 8) * SAP + ka + 8];
#pragma unroll
            for (int ni = 0; ni < 2; ni++)
                mma_f16(acc[mi][ni], A0, A1, A2, A3, Bf[ni][0], Bf[ni][1]);
        }
        if (kc < NC16 - 1)
            *(uint4*)(sB + ((kc + 1) & 1) * SB_BUF + nB * SBP + hp * 8) = pb;
        __syncthreads();
    }

    // ---- epilogue: stage C to smem (sA no longer needed) ----
#pragma unroll
    for (int mi = 0; mi < 2; mi++) {
        int R = mi * 16 + g;
#pragma unroll
        for (int ni = 0; ni < 2; ni++) {
            int col = wn * 16 + ni * 8 + 2 * t;
            sC[R * SCP + col]           = acc[mi][ni][0];
            sC[R * SCP + col + 1]       = acc[mi][ni][1];
            sC[(R + 8) * SCP + col]     = acc[mi][ni][2];
            sC[(R + 8) * SCP + col + 1] = acc[mi][ni][3];
        }
    }
    __syncthreads();

    // ---- bias + LayerNorm + relu + residual; write fp32 + fp16 mirror ----
    for (int i = 0; i < 4; i++) {
        int m = warp * 4 + i;
        float4 v = *(float4*)&sC[m * SCP + 4 * lane];
        float4 bi = __ldg(&((const float4*)bias_l)[lane]);
        v.x += bi.x; v.y += bi.y; v.z += bi.z; v.w += bi.w;
        float s = v.x + v.y + v.z + v.w;
#pragma unroll
        for (int o = 16; o; o >>= 1) s += __shfl_xor_sync(0xFFFFFFFFu, s, o);
        float mu = s * (1.0f / HH);
        float dx = v.x - mu, dy = v.y - mu, dz = v.z - mu, dw = v.w - mu;
        float q = dx * dx + dy * dy + dz * dz + dw * dw;
#pragma unroll
        for (int o = 16; o; o >>= 1) q += __shfl_xor_sync(0xFFFFFFFFu, q, o);
        float rs = rsqrtf(q * (1.0f / HH) + 1e-5f);
        float4 g4 = __ldg(&((const float4*)gam)[lane]);
        float4 b4 = __ldg(&((const float4*)bet)[lane]);
        float4 o4;
        o4.x = fmaxf(dx * rs * g4.x + b4.x, 0.f);
        o4.y = fmaxf(dy * rs * g4.y + b4.y, 0.f);
        o4.z = fmaxf(dz * rs * g4.z + b4.z, 0.f);
        o4.w = fmaxf(dw * rs * g4.w + b4.w, 0.f);
        if (residual) {
            float4 h4 = ((const float4*)(in + (size_t)(m0 + m) * HH))[lane];
            o4.x += h4.x; o4.y += h4.y; o4.z += h4.z; o4.w += h4.w;
        }
        size_t rowo = (size_t)(m0 + m) * HH;
        ((float4*)(out + rowo))[lane] = o4;
        uint2 hpk;
        *(__half2*)&hpk.x = __floats2half2_rn(o4.x, o4.y);
        *(__half2*)&hpk.y = __floats2half2_rn(o4.z, o4.w);
        ((uint2*)(hh_out + rowo))[lane] = hpk;
    }
}

// ---------------- head: hidden = relu(h @ W1 + b1) in smem; out = hidden @ W2 + b2 ----------------
#define KC   16
#define LDSA 136
__global__ void __launch_bounds__(256) k_head(
    const float* __restrict__ A1,
    const float* __restrict__ W1, const float* __restrict__ b1,
    const float* __restrict__ W2, const float* __restrict__ b2,
    float* __restrict__ outp)
{
    extern __shared__ __align__(16) float sU[];      // SMEM_HEAD bytes (dynamic)
    __shared__ float sW2[HH * OUTD];
    __shared__ float sb2[OUTD];
    float (*Ah)[LDSA] = (float(*)[LDSA])sU;
    float (*Al)[LDSA] = (float(*)[LDSA])(sU + KC * LDSA);
    float (*Bh)[LDSA] = (float(*)[LDSA])(sU + 2 * KC * LDSA);
    float (*Bl)[LDSA] = (float(*)[LDSA])(sU + 3 * KC * LDSA);
    float* sC = sU;

    int tid  = threadIdx.x;
    int warp = tid >> 5, lane = tid & 31;
    int wm = warp & 1, wn = warp >> 1;
    int g  = lane >> 2, t = lane & 3;
    int m0 = blockIdx.x * 128;

    for (int i = tid; i < HH * OUTD; i += 256) sW2[i] = W2[i];
    if (tid < OUTD) sb2[tid] = b2[tid];

    float acc[4][4][4];
#pragma unroll
    for (int i = 0; i < 4; i++)
#pragma unroll
        for (int j = 0; j < 4; j++)
#pragma unroll
            for (int c = 0; c < 4; c++) acc[i][j][c] = 0.f;

    for (int kk = 0; kk < HH; kk += KC) {
        {
            int m   = tid >> 1;
            int kq0 = (tid & 1) * 8;
#pragma unroll
            for (int q = 0; q < 2; q++) {
                float4 v = *(const float4*)(A1 + (size_t)(m0 + m) * HH + kk + kq0 + q * 4);
                float e[4] = {v.x, v.y, v.z, v.w};
#pragma unroll
                for (int u = 0; u < 4; u++) {
                    float hi = tf32r(e[u]);
                    Ah[kq0 + q * 4 + u][m] = hi;
                    Al[kq0 + q * 4 + u][m] = tf32r(e[u] - hi);
                }
            }
        }
        {
            const float* Bp = W1 + (size_t)kk * HH;
            int kr  = tid >> 4;
            int cc0 = (tid & 15) * 8;
#pragma unroll
            for (int q = 0; q < 2; q++) {
                float4 v = *(const float4*)(Bp + (size_t)kr * HH + cc0 + q * 4);
                float e[4] = {v.x, v.y, v.z, v.w};
#pragma unroll
                for (int u = 0; u < 4; u++) {
                    float hi = tf32r(e[u]);
                    Bh[kr][cc0 + q * 4 + u] = hi;
                    Bl[kr][cc0 + q * 4 + u] = tf32r(e[u] - hi);
                }
            }
        }
        __syncthreads();

#pragma unroll
        for (int ks = 0; ks < KC / 8; ks++) {
            int k0 = ks * 8;
            uint32_t bh[4][2], bl[4][2];
#pragma unroll
            for (int ni = 0; ni < 4; ni++) {
                int nb = wn * 32 + ni * 8 + g;
                bh[ni][0] = __float_as_uint(Bh[k0 + t    ][nb]);
                bh[ni][1] = __float_as_uint(Bh[k0 + t + 4][nb]);
                bl[ni][0] = __float_as_uint(Bl[k0 + t    ][nb]);
                bl[ni][1] = __float_as_uint(Bl[k0 + t + 4][nb]);
            }
#pragma unroll
            for (int mi = 0; mi < 4; mi++) {
                int R = wm * 64 + mi * 16 + g;
                uint32_t ah0 = __float_as_uint(Ah[k0 + t    ][R]);
                uint32_t ah1 = __float_as_uint(Ah[k0 + t    ][R + 8]);
                uint32_t ah2 = __float_as_uint(Ah[k0 + t + 4][R]);
                uint32_t ah3 = __float_as_uint(Ah[k0 + t + 4][R + 8]);
                uint32_t al0 = __float_as_uint(Al[k0 + t    ][R]);
                uint32_t al1 = __float_as_uint(Al[k0 + t    ][R + 8]);
                uint32_t al2 = __float_as_uint(Al[k0 + t + 4][R]);
                uint32_t al3 = __float_as_uint(Al[k0 + t + 4][R + 8]);
#pragma unroll
                for (int ni = 0; ni < 4; ni++) {
                    float* c = acc[mi][ni];
                    mma_tf32(c[0], c[1], c[2], c[3], ah0, ah1, ah2, ah3, bh[ni][0], bh[ni][1]);
                    mma_tf32(c[0], c[1], c[2], c[3], ah0, ah1, ah2, ah3, bl[ni][0], bl[ni][1]);
                    mma_tf32(c[0], c[1], c[2], c[3], al0, al1, al2, al3, bh[ni][0], bh[ni][1]);
                }
            }
        }
        __syncthreads();
    }

    // hidden (bias + relu) -> sC
#pragma unroll
    for (int ni = 0; ni < 4; ni++) {
        int col = wn * 32 + ni * 8 + 2 * t;
        float b0 = b1[col], bb1 = b1[col + 1];
#pragma unroll
        for (int mi = 0; mi < 4; mi++) {
            int R = wm * 64 + mi * 16 + g;
            float* c = acc[mi][ni];
            sC[R * SCP + col]           = fmaxf(c[0] + b0, 0.f);
            sC[R * SCP + col + 1]       = fmaxf(c[1] + bb1, 0.f);
            sC[(R + 8) * SCP + col]     = fmaxf(c[2] + b0, 0.f);
            sC[(R + 8) * SCP + col + 1] = fmaxf(c[3] + bb1, 0.f);
        }
    }
    __syncthreads();

    // tail: out[row, 0..7] = hidden[row,:] @ W2 + b2
    {
        int row = tid >> 1;
        int cb  = (tid & 1) * 4;
        float o0 = sb2[cb], o1 = sb2[cb + 1], o2 = sb2[cb + 2], o3 = sb2[cb + 3];
#pragma unroll 4
        for (int k = 0; k < HH; k++) {
            float hv = sC[row * SCP + k];
            float4 w = *(const float4*)&sW2[k * OUTD + cb];
            o0 += hv * w.x; o1 += hv * w.y; o2 += hv * w.z; o3 += hv * w.w;
        }
        *(float4*)(outp + (size_t)(m0 + row) * OUTD + cb) = make_float4(o0, o1, o2, o3);
    }
}

// ---------------- launch ----------------
extern "C" void kernel_launch(void* const* d_in, const int* in_sizes, int n_in,
                              void* d_out, int out_size) {
    const float* x     = (const float*)d_in[0];
    const void*  ei    = d_in[1];
    const void*  et    = d_in[2];
    const float* W_in  = (const float*)d_in[3];
    const float* b_in  = (const float*)d_in[4];
    const float* basis = (const float*)d_in[5];
    const float* comp  = (const float*)d_in[6];
    const float* root  = (const float*)d_in[7];
    const float* bias  = (const float*)d_in[8];
    const float* ln_g  = (const float*)d_in[9];
    const float* ln_b  = (const float*)d_in[10];
    const float* W1    = (const float*)d_in[11];
    const float* b1    = (const float*)d_in[12];
    const float* W2    = (const float*)d_in[13];
    const float* b2    = (const float*)d_in[14];

    void *p_h, *p_t, *p_hh0, *p_hh1, *p_wB;
    cudaGetSymbolAddress(&p_h,   g_h);
    cudaGetSymbolAddress(&p_t,   g_t);
    cudaGetSymbolAddress(&p_hh0, g_hh0);
    cudaGetSymbolAddress(&p_hh1, g_hh1);
    cudaGetSymbolAddress(&p_wB,  g_wB);
    cudaFuncSetAttribute(k_layer, cudaFuncAttributeMaxDynamicSharedMemorySize, SMEM_LAYER);
    cudaFuncSetAttribute(k_head,  cudaFuncAttributeMaxDynamicSharedMemorySize, SMEM_HEAD);

    // ---- one-time preprocessing ----
    k_detect<<<1, 256>>>((const int*)ei);
    k_zero_cnt<<<(NN * RR + 255) / 256, 256>>>();
    k_prep_count<<<EE / 256, 256>>>(ei, et);
    k_ps1<<<NN / 256, 256>>>();
    k_ps2<<<1, 512>>>();
    k_ps3<<<NN / 256, 256>>>();
    k_csr_scatter<<<EE / 256, 256>>>(ei, et);
    k_wconv<<<(LL * NC16 * 128 * 16 + 255) / 256, 256>>>(basis, root);
    k_inproj<<<NN / 8, 128>>>(x, W_in, b_in);

    // ---- fused layers (ping-pong fp32 + fp16 mirrors) ----
    float*  bufs[2] = {(float*)p_h, (float*)p_t};
    __half* hhb[2]  = {(__half*)p_hh0, (__half*)p_hh1};
    for (int i = 0; i < LL; i++) {
        k_layer<<<NN / TM, 256, SMEM_LAYER>>>(
            bufs[i & 1], bufs[(i + 1) & 1],
            hhb[i & 1], hhb[(i + 1) & 1],
            (const __half*)p_wB + (size_t)i * NC16 * 128 * 16,
            comp + i * RR * BB,
            bias + i * HH, ln_g + i * HH, ln_b + i * HH, i > 0 ? 1 : 0);
    }

    // ---- fused head ----
    k_head<<<NN / 128, 256, SMEM_HEAD>>>(bufs[LL & 1], W1, b1, W2, b2, (float*)d_out);
}

// round 14
// speedup vs baseline: 1.3634x; 1.0854x over previous
#include <cuda_runtime.h>
#include <cuda_fp16.h>
#include <cstdint>

#define NN   131072
#define EE   2097152
#define FF   32
#define HH   128
#define RR   10
#define BB   4
#define LL   3
#define OUTD 8

#define TM   32               // layer-kernel block rows (dst nodes)
#define SAP  648              // sA k-stride in halves (640 + 8 pad)
#define SBP  24               // sB row stride in halves (16 used + 8 pad)
#define SB_BUF (128 * SBP)    // halves per 16-k B buffer (3072)
#define SCP  132              // sC row stride in floats
#define NC16 40               // 16-wide K chunks (640 total)
#define SMEM_LAYER (TM * SAP * 2 + 2 * SB_BUF * 2)   // 41472 + 12288 = 53760 B

#define SAPH 136              // head sA k-stride in halves (128 + 8 pad)
#define SMEM_HEADF (TM * SCP * 4 + 2 * SB_BUF * 2)   // 16896 + 12288 = 29184 B

// ---------------- device scratch ----------------
__device__ __half g_hh0[(size_t)NN * HH];   // fp16 features (ping)
__device__ __half g_hh1[(size_t)NN * HH];   // fp16 features (pong)
__device__ __half g_wB [(size_t)LL * NC16 * 128 * 16]; // staged fp16 layer weights
__device__ __half g_wB1[(size_t)8 * 128 * 16];         // staged fp16 W1 (head)
__device__ float  g_cnt[NN * RR];
__device__ int    g_deg[NN];
__device__ int    g_row[NN + 1];
__device__ int    g_bsum[512];
__device__ int    g_cursor[NN];
__device__ int2   g_meta[EE];          // dst-sorted {src|rel<<20, bits(1/cnt)}
__device__ int    g_is64;

// ---------------- helpers ----------------
__device__ __forceinline__ void mma_f16(float* c,
                                        uint32_t a0, uint32_t a1, uint32_t a2, uint32_t a3,
                                        uint32_t b0, uint32_t b1) {
    asm volatile(
        "mma.sync.aligned.m16n8k16.row.col.f32.f16.f16.f32 "
        "{%0,%1,%2,%3}, {%4,%5,%6,%7}, {%8,%9}, {%0,%1,%2,%3};"
        : "+f"(c[0]), "+f"(c[1]), "+f"(c[2]), "+f"(c[3])
        : "r"(a0), "r"(a1), "r"(a2), "r"(a3), "r"(b0), "r"(b1));
}

// ---------------- dtype detect ----------------
__global__ void k_detect(const int* __restrict__ ei) {
    __shared__ int cnt;
    if (threadIdx.x == 0) cnt = 0;
    __syncthreads();
    if (ei[threadIdx.x * 2 + 1] != 0) atomicAdd(&cnt, 1);
    __syncthreads();
    if (threadIdx.x == 0) g_is64 = (cnt == 0) ? 1 : 0;
}

__global__ void k_zero_cnt() {
    int i = blockIdx.x * blockDim.x + threadIdx.x;
    if (i < NN * RR) g_cnt[i] = 0.0f;
    if (i < NN) g_deg[i] = 0;
}

// ---------------- decode + count ----------------
__global__ void k_prep_count(const void* __restrict__ ei_raw, const void* __restrict__ et_raw) {
    int e = blockIdx.x * blockDim.x + threadIdx.x;
    if (e >= EE) return;
    int d, t;
    if (g_is64) {
        const long long* ei = (const long long*)ei_raw;
        const long long* et = (const long long*)et_raw;
        d = (int)ei[(size_t)EE + e];
        t = (int)et[e];
    } else {
        const int* ei = (const int*)ei_raw;
        const int* et = (const int*)et_raw;
        d = ei[EE + e];
        t = et[e];
    }
    atomicAdd(&g_cnt[d * RR + t], 1.0f);
    atomicAdd(&g_deg[d], 1);
}

// ---------------- prefix scan over node degrees ----------------
__global__ void k_ps1() {
    __shared__ int sh[256];
    int i = blockIdx.x * 256 + threadIdx.x;
    int v = g_deg[i];
    sh[threadIdx.x] = v;
    __syncthreads();
#pragma unroll
    for (int o = 1; o < 256; o <<= 1) {
        int t = (threadIdx.x >= o) ? sh[threadIdx.x - o] : 0;
        __syncthreads();
        sh[threadIdx.x] += t;
        __syncthreads();
    }
    g_row[i] = sh[threadIdx.x] - v;
    if (threadIdx.x == 255) g_bsum[blockIdx.x] = sh[255];
}

__global__ void k_ps2() {
    __shared__ int sh[512];
    int v = g_bsum[threadIdx.x];
    sh[threadIdx.x] = v;
    __syncthreads();
#pragma unroll
    for (int o = 1; o < 512; o <<= 1) {
        int t = (threadIdx.x >= o) ? sh[threadIdx.x - o] : 0;
        __syncthreads();
        sh[threadIdx.x] += t;
        __syncthreads();
    }
    g_bsum[threadIdx.x] = sh[threadIdx.x] - v;
}

__global__ void k_ps3() {
    int i = blockIdx.x * 256 + threadIdx.x;
    int r = g_row[i] + g_bsum[i >> 8];
    g_row[i] = r;
    g_cursor[i] = r;
    if (i == 0) g_row[NN] = EE;
}

// ---------------- CSR scatter (re-decodes raw edges) ----------------
__global__ void k_csr_scatter(const void* __restrict__ ei_raw, const void* __restrict__ et_raw) {
    int e = blockIdx.x * blockDim.x + threadIdx.x;
    if (e >= EE) return;
    int s, d, t;
    if (g_is64) {
        const long long* ei = (const long long*)ei_raw;
        const long long* et = (const long long*)et_raw;
        s = (int)ei[e];
        d = (int)ei[(size_t)EE + e];
        t = (int)et[e];
    } else {
        const int* ei = (const int*)ei_raw;
        const int* et = (const int*)et_raw;
        s = ei[e];
        d = ei[EE + e];
        t = et[e];
    }
    int pos = atomicAdd(&g_cursor[d], 1);
    float inv = 1.0f / fmaxf(g_cnt[d * RR + t], 1.0f);
    g_meta[pos] = make_int2(s | (t << 20), __float_as_int(inv));
}

// ---------------- weight preconvert: basis||root -> staged fp16 [NC16][128][16] ----------------
__global__ void k_wconv(const float* __restrict__ basis, const float* __restrict__ root) {
    int idx = blockIdx.x * blockDim.x + threadIdx.x;
    if (idx >= LL * NC16 * 128 * 16) return;
    int l   = idx / (NC16 * 128 * 16);
    int rem = idx % (NC16 * 128 * 16);
    int kc  = rem >> 11;
    int n   = (rem >> 4) & 127;
    int kr  = rem & 15;
    int kg  = kc * 16 + kr;
    float v = (kg < 512) ? basis[(size_t)l * 512 * HH + (size_t)kg * HH + n]
                         : root [(size_t)l * HH * HH + (size_t)(kg - 512) * HH + n];
    g_wB[idx] = __float2half_rn(v);
}

// ---------------- W1 preconvert -> staged fp16 [8][128][16] ----------------
__global__ void k_wconvh(const float* __restrict__ W1) {
    int idx = blockIdx.x * blockDim.x + threadIdx.x;
    if (idx >= 8 * 128 * 16) return;
    int kc = idx >> 11;
    int n  = (idx >> 4) & 127;
    int kr = idx & 15;
    g_wB1[idx] = __float2half_rn(W1[(size_t)(kc * 16 + kr) * HH + n]);
}

// ---------------- input projection (fp16 mirror only) ----------------
__global__ void k_inproj(const float* __restrict__ x, const float* __restrict__ W,
                         const float* __restrict__ b) {
    __shared__ float Ws[FF * HH];
    __shared__ float xs[8][FF];
    int tid = threadIdx.x;
    for (int i = tid; i < FF * HH; i += 128) Ws[i] = W[i];
    int n0 = blockIdx.x * 8;
    for (int i = tid; i < 8 * FF; i += 128) xs[i / FF][i % FF] = x[(size_t)n0 * FF + i];
    __syncthreads();
    float bj = b[tid];
#pragma unroll
    for (int u = 0; u < 8; u++) {
        float acc = bj;
#pragma unroll
        for (int k = 0; k < FF; k++) acc += xs[u][k] * Ws[k * HH + tid];
        g_hh0[(size_t)(n0 + u) * HH + tid] = __float2half_rn(acc);
    }
}

// ================= fused RGCN layer (TM=32, 4 blocks/SM, fp16 feature path) =================
__global__ void __launch_bounds__(256, 4) k_layer(
    const __half* __restrict__ hh_in, __half* __restrict__ hh_out,
    const __half* __restrict__ wB_l,
    const float* __restrict__ comp_l, const float* __restrict__ bias_l,
    const float* __restrict__ gam, const float* __restrict__ bet, int residual)
{
    extern __shared__ __align__(16) char dyn[];
    __half* sA = (__half*)dyn;                       // [TM][SAP]
    __half* sB = (__half*)(dyn + TM * SAP * 2);      // 2 x [128][SBP]
    float*  sC = (float*)dyn;                        // epilogue reuse [TM][SCP]
    __shared__ float s_comp[RR * BB];

    int tid = threadIdx.x, warp = tid >> 5, lane = tid & 31;
    int m0 = blockIdx.x * TM;
    if (tid < RR * BB) s_comp[tid] = comp_l[tid];

    // ---- stage h (root planes 512..639) from fp16 features ----
    for (int i = tid; i < TM * 16; i += 256) {
        int m = i >> 4, c8 = i & 15;
        *(uint4*)(sA + m * SAP + 512 + c8 * 8) =
            ((const uint4*)(hh_in + (size_t)(m0 + m) * HH))[c8];
    }

    // ---- prologue: stage B chunk 0 into buf 0 ----
    int nB = tid >> 1, hp = tid & 1;
    {
        uint4 p0 = ((const uint4*)wB_l)[(size_t)(0 * 128 + nB) * 2 + hp];
        *(uint4*)(sB + 0 * SB_BUF + nB * SBP + hp * 8) = p0;
    }
    __syncthreads();

    // ---- aggregation: 4 nodes per warp, fp32 accumulators, 4-way unrolled ----
#define ACC_EDGE(mt, r)                                                       \
    {                                                                         \
        int   t_  = mt.x >> 20;                                               \
        float iv_ = __int_as_float(mt.y);                                     \
        float c0 = s_comp[t_ * BB + 0] * iv_;                                 \
        float c1 = s_comp[t_ * BB + 1] * iv_;                                 \
        float c2 = s_comp[t_ * BB + 2] * iv_;                                 \
        float c3 = s_comp[t_ * BB + 3] * iv_;                                 \
        float2 p0 = __half22float2(*(__half2*)&r.x);                          \
        float2 p1 = __half22float2(*(__half2*)&r.y);                          \
        a0.x += c0 * p0.x; a0.y += c0 * p0.y; a0.z += c0 * p1.x; a0.w += c0 * p1.y; \
        a1.x += c1 * p0.x; a1.y += c1 * p0.y; a1.z += c1 * p1.x; a1.w += c1 * p1.y; \
        a2.x += c2 * p0.x; a2.y += c2 * p0.y; a2.z += c2 * p1.x; a2.w += c2 * p1.y; \
        a3.x += c3 * p0.x; a3.y += c3 * p0.y; a3.z += c3 * p1.x; a3.w += c3 * p1.y; \
    }

    for (int ii = 0; ii < 4; ii++) {
        int m = warp * 4 + ii;
        int node = m0 + m;
        int beg = g_row[node], end = g_row[node + 1];
        float4 a0 = make_float4(0.f, 0.f, 0.f, 0.f);
        float4 a1 = a0, a2 = a0, a3 = a0;
        int e = beg;
        for (; e + 4 <= end; e += 4) {
            int2 m0_ = __ldg(&g_meta[e + 0]);
            int2 m1_ = __ldg(&g_meta[e + 1]);
            int2 m2_ = __ldg(&g_meta[e + 2]);
            int2 m3_ = __ldg(&g_meta[e + 3]);
            uint2 r0 = __ldg((const uint2*)(hh_in + (size_t)(m0_.x & 0xFFFFF) * HH) + lane);
            uint2 r1 = __ldg((const uint2*)(hh_in + (size_t)(m1_.x & 0xFFFFF) * HH) + lane);
            uint2 r2 = __ldg((const uint2*)(hh_in + (size_t)(m2_.x & 0xFFFFF) * HH) + lane);
            uint2 r3 = __ldg((const uint2*)(hh_in + (size_t)(m3_.x & 0xFFFFF) * HH) + lane);
            ACC_EDGE(m0_, r0);
            ACC_EDGE(m1_, r1);
            ACC_EDGE(m2_, r2);
            ACC_EDGE(m3_, r3);
        }
        for (; e < end; e++) {
            int2 mt = __ldg(&g_meta[e]);
            uint2 rr = __ldg((const uint2*)(hh_in + (size_t)(mt.x & 0xFFFFF) * HH) + lane);
            ACC_EDGE(mt, rr);
        }
        __half* dst = sA + m * SAP + 4 * lane;
        *(__half2*)(dst + 0 * 128 + 0) = __floats2half2_rn(a0.x, a0.y);
        *(__half2*)(dst + 0 * 128 + 2) = __floats2half2_rn(a0.z, a0.w);
        *(__half2*)(dst + 1 * 128 + 0) = __floats2half2_rn(a1.x, a1.y);
        *(__half2*)(dst + 1 * 128 + 2) = __floats2half2_rn(a1.z, a1.w);
        *(__half2*)(dst + 2 * 128 + 0) = __floats2half2_rn(a2.x, a2.y);
        *(__half2*)(dst + 2 * 128 + 2) = __floats2half2_rn(a2.z, a2.w);
        *(__half2*)(dst + 3 * 128 + 0) = __floats2half2_rn(a3.x, a3.y);
        *(__half2*)(dst + 3 * 128 + 2) = __floats2half2_rn(a3.z, a3.w);
    }
#undef ACC_EDGE
    __syncthreads();

    // ---- GEMM: [TM x 640] @ [640 x 128], fp16 mma, 1m x 8n warp grid ----
    int wn = warp;                   // warp tile: 32 rows x 16 cols
    int g = lane >> 2, t = lane & 3;
    float acc[2][2][4];
#pragma unroll
    for (int i = 0; i < 2; i++)
#pragma unroll
        for (int j = 0; j < 2; j++)
#pragma unroll
            for (int c = 0; c < 4; c++) acc[i][j][c] = 0.f;

    uint4 pb;
    for (int kc = 0; kc < NC16; kc++) {
        if (kc < NC16 - 1)
            pb = ((const uint4*)wB_l)[(size_t)((kc + 1) * 128 + nB) * 2 + hp];
        const __half* bb = sB + (kc & 1) * SB_BUF;
        int ka = kc * 16 + 2 * t;
        uint32_t Bf[2][2];
#pragma unroll
        for (int ni = 0; ni < 2; ni++) {
            int n = wn * 16 + ni * 8 + g;
            Bf[ni][0] = *(const uint32_t*)&bb[n * SBP + 2 * t];
            Bf[ni][1] = *(const uint32_t*)&bb[n * SBP + 2 * t + 8];
        }
#pragma unroll
        for (int mi = 0; mi < 2; mi++) {
            int R = mi * 16 + g;
            uint32_t A0 = *(const uint32_t*)&sA[R * SAP + ka];
            uint32_t A1 = *(const uint32_t*)&sA[(R + 8) * SAP + ka];
            uint32_t A2 = *(const uint32_t*)&sA[R * SAP + ka + 8];
            uint32_t A3 = *(const uint32_t*)&sA[(R + 8) * SAP + ka + 8];
#pragma unroll
            for (int ni = 0; ni < 2; ni++)
                mma_f16(acc[mi][ni], A0, A1, A2, A3, Bf[ni][0], Bf[ni][1]);
        }
        if (kc < NC16 - 1)
            *(uint4*)(sB + ((kc + 1) & 1) * SB_BUF + nB * SBP + hp * 8) = pb;
        __syncthreads();
    }

    // ---- epilogue: stage C to smem (sA no longer needed) ----
#pragma unroll
    for (int mi = 0; mi < 2; mi++) {
        int R = mi * 16 + g;
#pragma unroll
        for (int ni = 0; ni < 2; ni++) {
            int col = wn * 16 + ni * 8 + 2 * t;
            sC[R * SCP + col]           = acc[mi][ni][0];
            sC[R * SCP + col + 1]       = acc[mi][ni][1];
            sC[(R + 8) * SCP + col]     = acc[mi][ni][2];
            sC[(R + 8) * SCP + col + 1] = acc[mi][ni][3];
        }
    }
    __syncthreads();

    // ---- bias + LayerNorm + relu + residual(fp16); write fp16 features ----
    for (int i = 0; i < 4; i++) {
        int m = warp * 4 + i;
        size_t rowo = (size_t)(m0 + m) * HH;
        float4 v = *(float4*)&sC[m * SCP + 4 * lane];
        float4 bi = __ldg(&((const float4*)bias_l)[lane]);
        v.x += bi.x; v.y += bi.y; v.z += bi.z; v.w += bi.w;
        float s = v.x + v.y + v.z + v.w;
#pragma unroll
        for (int o = 16; o; o >>= 1) s += __shfl_xor_sync(0xFFFFFFFFu, s, o);
        float mu = s * (1.0f / HH);
        float dx = v.x - mu, dy = v.y - mu, dz = v.z - mu, dw = v.w - mu;
        float q = dx * dx + dy * dy + dz * dz + dw * dw;
#pragma unroll
        for (int o = 16; o; o >>= 1) q += __shfl_xor_sync(0xFFFFFFFFu, q, o);
        float rs = rsqrtf(q * (1.0f / HH) + 1e-5f);
        float4 g4 = __ldg(&((const float4*)gam)[lane]);
        float4 b4 = __ldg(&((const float4*)bet)[lane]);
        float4 o4;
        o4.x = fmaxf(dx * rs * g4.x + b4.x, 0.f);
        o4.y = fmaxf(dy * rs * g4.y + b4.y, 0.f);
        o4.z = fmaxf(dz * rs * g4.z + b4.z, 0.f);
        o4.w = fmaxf(dw * rs * g4.w + b4.w, 0.f);
        if (residual) {
            uint2 hv = ((const uint2*)(hh_in + rowo))[lane];
            float2 h0 = __half22float2(*(__half2*)&hv.x);
            float2 h1 = __half22float2(*(__half2*)&hv.y);
            o4.x += h0.x; o4.y += h0.y; o4.z += h1.x; o4.w += h1.y;
        }
        uint2 hpk;
        *(__half2*)&hpk.x = __floats2half2_rn(o4.x, o4.y);
        *(__half2*)&hpk.y = __floats2half2_rn(o4.z, o4.w);
        ((uint2*)(hh_out + rowo))[lane] = hpk;
    }
}

// ================= head: hidden = relu(h @ W1 + b1) fp16-mma; out = hidden @ W2 + b2 =================
__global__ void __launch_bounds__(256, 4) k_headf(
    const __half* __restrict__ hh,
    const float* __restrict__ b1,
    const float* __restrict__ W2, const float* __restrict__ b2,
    float* __restrict__ outp)
{
    extern __shared__ __align__(16) char dyn[];
    __half* sA = (__half*)dyn;                       // [TM][SAPH] (aliased with sC)
    float*  sC = (float*)dyn;                        // [TM][SCP]
    __half* sB = (__half*)(dyn + TM * SCP * 4);      // 2 x [128][SBP]
    __shared__ float sW2[HH * OUTD];
    __shared__ float sb2[OUTD];

    int tid = threadIdx.x, warp = tid >> 5, lane = tid & 31;
    int m0 = blockIdx.x * TM;

    for (int i = tid; i < HH * OUTD; i += 256) sW2[i] = W2[i];
    if (tid < OUTD) sb2[tid] = b2[tid];

    // ---- stage A: 32 rows x 128 halves ----
    for (int i = tid; i < TM * 16; i += 256) {
        int m = i >> 4, c8 = i & 15;
        *(uint4*)(sA + m * SAPH + c8 * 8) =
            ((const uint4*)(hh + (size_t)(m0 + m) * HH))[c8];
    }

    // ---- prologue: stage W1 chunk 0 ----
    int nB = tid >> 1, hp = tid & 1;
    {
        uint4 p0 = ((const uint4*)g_wB1)[(size_t)(0 * 128 + nB) * 2 + hp];
        *(uint4*)(sB + 0 * SB_BUF + nB * SBP + hp * 8) = p0;
    }
    __syncthreads();

    // ---- GEMM: [32 x 128] @ [128 x 128], 8 chunks ----
    int wn = warp;
    int g = lane >> 2, t = lane & 3;
    float acc[2][2][4];
#pragma unroll
    for (int i = 0; i < 2; i++)
#pragma unroll
        for (int j = 0; j < 2; j++)
#pragma unroll
            for (int c = 0; c < 4; c++) acc[i][j][c] = 0.f;

    uint4 pb;
#pragma unroll
    for (int kc = 0; kc < 8; kc++) {
        if (kc < 7)
            pb = ((const uint4*)g_wB1)[(size_t)((kc + 1) * 128 + nB) * 2 + hp];
        const __half* bb = sB + (kc & 1) * SB_BUF;
        int ka = kc * 16 + 2 * t;
        uint32_t Bf[2][2];
#pragma unroll
        for (int ni = 0; ni < 2; ni++) {
            int n = wn * 16 + ni * 8 + g;
            Bf[ni][0] = *(const uint32_t*)&bb[n * SBP + 2 * t];
            Bf[ni][1] = *(const uint32_t*)&bb[n * SBP + 2 * t + 8];
        }
#pragma unroll
        for (int mi = 0; mi < 2; mi++) {
            int R = mi * 16 + g;
            uint32_t A0 = *(const uint32_t*)&sA[R * SAPH + ka];
            uint32_t A1 = *(const uint32_t*)&sA[(R + 8) * SAPH + ka];
            uint32_t A2 = *(const uint32_t*)&sA[R * SAPH + ka + 8];
            uint32_t A3 = *(const uint32_t*)&sA[(R + 8) * SAPH + ka + 8];
#pragma unroll
            for (int ni = 0; ni < 2; ni++)
                mma_f16(acc[mi][ni], A0, A1, A2, A3, Bf[ni][0], Bf[ni][1]);
        }
        if (kc < 7)
            *(uint4*)(sB + ((kc + 1) & 1) * SB_BUF + nB * SBP + hp * 8) = pb;
        __syncthreads();
    }

    // ---- hidden (bias + relu) -> sC (overwrites sA; all reads done) ----
#pragma unroll
    for (int mi = 0; mi < 2; mi++) {
        int R = mi * 16 + g;
#pragma unroll
        for (int ni = 0; ni < 2; ni++) {
            int col = wn * 16 + ni * 8 + 2 * t;
            float b0 = b1[col], bb1 = b1[col + 1];
            sC[R * SCP + col]           = fmaxf(acc[mi][ni][0] + b0, 0.f);
            sC[R * SCP + col + 1]       = fmaxf(acc[mi][ni][1] + bb1, 0.f);
            sC[(R + 8) * SCP + col]     = fmaxf(acc[mi][ni][2] + b0, 0.f);
            sC[(R + 8) * SCP + col + 1] = fmaxf(acc[mi][ni][3] + bb1, 0.f);
        }
    }
    __syncthreads();

    // ---- tail: out[row, 0..7] = hidden[row,:] @ W2 + b2 ----
    {
        int row = tid >> 3;          // 0..31
        int col = tid & 7;
        float o = sb2[col];
#pragma unroll 4
        for (int k = 0; k < HH; k++)
            o += sC[row * SCP + k] * sW2[k * OUTD + col];
        outp[(size_t)(m0 + row) * OUTD + col] = o;
    }
}

// ---------------- launch ----------------
extern "C" void kernel_launch(void* const* d_in, const int* in_sizes, int n_in,
                              void* d_out, int out_size) {
    const float* x     = (const float*)d_in[0];
    const void*  ei    = d_in[1];
    const void*  et    = d_in[2];
    const float* W_in  = (const float*)d_in[3];
    const float* b_in  = (const float*)d_in[4];
    const float* basis = (const float*)d_in[5];
    const float* comp  = (const float*)d_in[6];
    const float* root  = (const float*)d_in[7];
    const float* bias  = (const float*)d_in[8];
    const float* ln_g  = (const float*)d_in[9];
    const float* ln_b  = (const float*)d_in[10];
    const float* W1    = (const float*)d_in[11];
    const float* b1    = (const float*)d_in[12];
    const float* W2    = (const float*)d_in[13];
    const float* b2    = (const float*)d_in[14];

    void *p_hh0, *p_hh1, *p_wB;
    cudaGetSymbolAddress(&p_hh0, g_hh0);
    cudaGetSymbolAddress(&p_hh1, g_hh1);
    cudaGetSymbolAddress(&p_wB,  g_wB);
    cudaFuncSetAttribute(k_layer, cudaFuncAttributeMaxDynamicSharedMemorySize, SMEM_LAYER);
    cudaFuncSetAttribute(k_headf, cudaFuncAttributeMaxDynamicSharedMemorySize, SMEM_HEADF);

    // ---- one-time preprocessing ----
    k_detect<<<1, 256>>>((const int*)ei);
    k_zero_cnt<<<(NN * RR + 255) / 256, 256>>>();
    k_prep_count<<<EE / 256, 256>>>(ei, et);
    k_ps1<<<NN / 256, 256>>>();
    k_ps2<<<1, 512>>>();
    k_ps3<<<NN / 256, 256>>>();
    k_csr_scatter<<<EE / 256, 256>>>(ei, et);
    k_wconv<<<(LL * NC16 * 128 * 16 + 255) / 256, 256>>>(basis, root);
    k_wconvh<<<(8 * 128 * 16 + 255) / 256, 256>>>(W1);
    k_inproj<<<NN / 8, 128>>>(x, W_in, b_in);

    // ---- fused layers (ping-pong fp16 features) ----
    __half* hhb[2] = {(__half*)p_hh0, (__half*)p_hh1};
    for (int i = 0; i < LL; i++) {
        k_layer<<<NN / TM, 256, SMEM_LAYER>>>(
            hhb[i & 1], hhb[(i + 1) & 1],
            (const __half*)p_wB + (size_t)i * NC16 * 128 * 16,
            comp + i * RR * BB,
            bias + i * HH, ln_g + i * HH, ln_b + i * HH, i > 0 ? 1 : 0);
    }

    // ---- fp16 head ----
    k_headf<<<NN / TM, 256, SMEM_HEADF>>>(hhb[LL & 1], b1, W2, b2, (float*)d_out);
}

// round 15
// speedup vs baseline: 1.6379x; 1.2013x over previous
#include <cuda_runtime.h>
#include <cuda_fp16.h>
#include <cstdint>

#define NN   131072
#define EE   2097152
#define FF   32
#define HH   128
#define RR   10
#define BB   4
#define LL   3
#define OUTD 8

#define TM   32               // layer-kernel block rows (dst nodes)
#define SAP  648              // sA k-stride in halves (640 + 8 pad)
#define SCP  132              // sC row stride in floats
#define NC16 40               // 16-wide K chunks (640 total)
#define SMEM_LAYER (TM * SAP * 2)                    // 41472 B
#define SAPH 136              // head sA k-stride in halves (128 + 8 pad)
#define SMEM_HEADF (TM * SCP * 4)                    // 16896 B

// ---------------- device scratch ----------------
__device__ __half g_hh0[(size_t)NN * HH];   // fp16 features (ping)
__device__ __half g_hh1[(size_t)NN * HH];   // fp16 features (pong)
__device__ __half g_wB [(size_t)LL * NC16 * 128 * 16]; // staged fp16 layer weights
__device__ __half g_wB1[(size_t)8 * 128 * 16];         // staged fp16 W1 (head)
__device__ float  g_cnt[NN * RR];
__device__ int    g_row[NN + 1];
__device__ int    g_bsum[512];
__device__ int    g_cursor[NN];
__device__ int2   g_meta[EE];          // dst-sorted {src|rel<<20, bits(1/cnt)}
__device__ int    g_is64;

// ---------------- helpers ----------------
__device__ __forceinline__ void mma_f16(float* c,
                                        uint32_t a0, uint32_t a1, uint32_t a2, uint32_t a3,
                                        uint32_t b0, uint32_t b1) {
    asm volatile(
        "mma.sync.aligned.m16n8k16.row.col.f32.f16.f16.f32 "
        "{%0,%1,%2,%3}, {%4,%5,%6,%7}, {%8,%9}, {%0,%1,%2,%3};"
        : "+f"(c[0]), "+f"(c[1]), "+f"(c[2]), "+f"(c[3])
        : "r"(a0), "r"(a1), "r"(a2), "r"(a3), "r"(b0), "r"(b1));
}

// ---------------- dtype detect ----------------
__global__ void k_detect(const int* __restrict__ ei) {
    __shared__ int cnt;
    if (threadIdx.x == 0) cnt = 0;
    __syncthreads();
    if (ei[threadIdx.x * 2 + 1] != 0) atomicAdd(&cnt, 1);
    __syncthreads();
    if (threadIdx.x == 0) g_is64 = (cnt == 0) ? 1 : 0;
}

__global__ void k_zero_cnt() {
    int i = blockIdx.x * blockDim.x + threadIdx.x;
    if (i < NN * RR) g_cnt[i] = 0.0f;
}

// ---------------- decode + per-(dst,rel) count ----------------
__global__ void k_prep_count(const void* __restrict__ ei_raw, const void* __restrict__ et_raw) {
    int e = blockIdx.x * blockDim.x + threadIdx.x;
    if (e >= EE) return;
    int d, t;
    if (g_is64) {
        const long long* ei = (const long long*)ei_raw;
        const long long* et = (const long long*)et_raw;
        d = (int)ei[(size_t)EE + e];
        t = (int)et[e];
    } else {
        const int* ei = (const int*)ei_raw;
        const int* et = (const int*)et_raw;
        d = ei[EE + e];
        t = et[e];
    }
    atomicAdd(&g_cnt[d * RR + t], 1.0f);
}

// ---------------- prefix scan over node degrees (derived from g_cnt) ----------------
__global__ void k_ps1() {
    __shared__ int sh[256];
    int i = blockIdx.x * 256 + threadIdx.x;
    int v = 0;
#pragma unroll
    for (int r = 0; r < RR; r++) v += (int)g_cnt[i * RR + r];
    sh[threadIdx.x] = v;
    __syncthreads();
#pragma unroll
    for (int o = 1; o < 256; o <<= 1) {
        int t = (threadIdx.x >= o) ? sh[threadIdx.x - o] : 0;
        __syncthreads();
        sh[threadIdx.x] += t;
        __syncthreads();
    }
    g_row[i] = sh[threadIdx.x] - v;
    if (threadIdx.x == 255) g_bsum[blockIdx.x] = sh[255];
}

__global__ void k_ps2() {
    __shared__ int sh[512];
    int v = g_bsum[threadIdx.x];
    sh[threadIdx.x] = v;
    __syncthreads();
#pragma unroll
    for (int o = 1; o < 512; o <<= 1) {
        int t = (threadIdx.x >= o) ? sh[threadIdx.x - o] : 0;
        __syncthreads();
        sh[threadIdx.x] += t;
        __syncthreads();
    }
    g_bsum[threadIdx.x] = sh[threadIdx.x] - v;
}

__global__ void k_ps3() {
    int i = blockIdx.x * 256 + threadIdx.x;
    int r = g_row[i] + g_bsum[i >> 8];
    g_row[i] = r;
    g_cursor[i] = r;
    if (i == 0) g_row[NN] = EE;
}

// ---------------- CSR scatter (re-decodes raw edges) ----------------
__global__ void k_csr_scatter(const void* __restrict__ ei_raw, const void* __restrict__ et_raw) {
    int e = blockIdx.x * blockDim.x + threadIdx.x;
    if (e >= EE) return;
    int s, d, t;
    if (g_is64) {
        const long long* ei = (const long long*)ei_raw;
        const long long* et = (const long long*)et_raw;
        s = (int)ei[e];
        d = (int)ei[(size_t)EE + e];
        t = (int)et[e];
    } else {
        const int* ei = (const int*)ei_raw;
        const int* et = (const int*)et_raw;
        s = ei[e];
        d = ei[EE + e];
        t = et[e];
    }
    int pos = atomicAdd(&g_cursor[d], 1);
    float inv = 1.0f / fmaxf(g_cnt[d * RR + t], 1.0f);
    g_meta[pos] = make_int2(s | (t << 20), __float_as_int(inv));
}

// ---------------- weight preconvert: basis||root -> staged fp16 [NC16][128][16] ----------------
__global__ void k_wconv(const float* __restrict__ basis, const float* __restrict__ root) {
    int idx = blockIdx.x * blockDim.x + threadIdx.x;
    if (idx >= LL * NC16 * 128 * 16) return;
    int l   = idx / (NC16 * 128 * 16);
    int rem = idx % (NC16 * 128 * 16);
    int kc  = rem >> 11;
    int n   = (rem >> 4) & 127;
    int kr  = rem & 15;
    int kg  = kc * 16 + kr;
    float v = (kg < 512) ? basis[(size_t)l * 512 * HH + (size_t)kg * HH + n]
                         : root [(size_t)l * HH * HH + (size_t)(kg - 512) * HH + n];
    g_wB[idx] = __float2half_rn(v);
}

// ---------------- W1 preconvert -> staged fp16 [8][128][16] ----------------
__global__ void k_wconvh(const float* __restrict__ W1) {
    int idx = blockIdx.x * blockDim.x + threadIdx.x;
    if (idx >= 8 * 128 * 16) return;
    int kc = idx >> 11;
    int n  = (idx >> 4) & 127;
    int kr = idx & 15;
    g_wB1[idx] = __float2half_rn(W1[(size_t)(kc * 16 + kr) * HH + n]);
}

// ---------------- input projection (fp16 features only) ----------------
__global__ void k_inproj(const float* __restrict__ x, const float* __restrict__ W,
                         const float* __restrict__ b) {
    __shared__ float Ws[FF * HH];
    __shared__ float xs[8][FF];
    int tid = threadIdx.x;
    for (int i = tid; i < FF * HH; i += 128) Ws[i] = W[i];
    int n0 = blockIdx.x * 8;
    for (int i = tid; i < 8 * FF; i += 128) xs[i / FF][i % FF] = x[(size_t)n0 * FF + i];
    __syncthreads();
    float bj = b[tid];
#pragma unroll
    for (int u = 0; u < 8; u++) {
        float acc = bj;
#pragma unroll
        for (int k = 0; k < FF; k++) acc += xs[u][k] * Ws[k * HH + tid];
        g_hh0[(size_t)(n0 + u) * HH + tid] = __float2half_rn(acc);
    }
}

// ================= fused RGCN layer (TM=32, 4 blocks/SM, barrier-free GEMM) =================
__global__ void __launch_bounds__(256, 4) k_layer(
    const __half* __restrict__ hh_in, __half* __restrict__ hh_out,
    const __half* __restrict__ wB_l,
    const float* __restrict__ comp_l, const float* __restrict__ bias_l,
    const float* __restrict__ gam, const float* __restrict__ bet, int residual)
{
    extern __shared__ __align__(16) char dyn[];
    __half* sA = (__half*)dyn;                       // [TM][SAP]
    float*  sC = (float*)dyn;                        // epilogue reuse [TM][SCP]
    __shared__ float s_comp[RR * BB];

    int tid = threadIdx.x, warp = tid >> 5, lane = tid & 31;
    int m0 = blockIdx.x * TM;
    if (tid < RR * BB) s_comp[tid] = comp_l[tid];

    // ---- stage h (root planes 512..639) from fp16 features ----
    for (int i = tid; i < TM * 16; i += 256) {
        int m = i >> 4, c8 = i & 15;
        *(uint4*)(sA + m * SAP + 512 + c8 * 8) =
            ((const uint4*)(hh_in + (size_t)(m0 + m) * HH))[c8];
    }
    __syncthreads();

    // ---- aggregation: 4 nodes per warp, fp32 accumulators, 4-way unrolled ----
#define ACC_EDGE(mt, r)                                                       \
    {                                                                         \
        int   t_  = mt.x >> 20;                                               \
        float iv_ = __int_as_float(mt.y);                                     \
        float c0 = s_comp[t_ * BB + 0] * iv_;                                 \
        float c1 = s_comp[t_ * BB + 1] * iv_;                                 \
        float c2 = s_comp[t_ * BB + 2] * iv_;                                 \
        float c3 = s_comp[t_ * BB + 3] * iv_;                                 \
        float2 p0 = __half22float2(*(__half2*)&r.x);                          \
        float2 p1 = __half22float2(*(__half2*)&r.y);                          \
        a0.x += c0 * p0.x; a0.y += c0 * p0.y; a0.z += c0 * p1.x; a0.w += c0 * p1.y; \
        a1.x += c1 * p0.x; a1.y += c1 * p0.y; a1.z += c1 * p1.x; a1.w += c1 * p1.y; \
        a2.x += c2 * p0.x; a2.y += c2 * p0.y; a2.z += c2 * p1.x; a2.w += c2 * p1.y; \
        a3.x += c3 * p0.x; a3.y += c3 * p0.y; a3.z += c3 * p1.x; a3.w += c3 * p1.y; \
    }

    for (int ii = 0; ii < 4; ii++) {
        int m = warp * 4 + ii;
        int node = m0 + m;
        int beg = g_row[node], end = g_row[node + 1];
        float4 a0 = make_float4(0.f, 0.f, 0.f, 0.f);
        float4 a1 = a0, a2 = a0, a3 = a0;
        int e = beg;
        for (; e + 4 <= end; e += 4) {
            int2 m0_ = __ldg(&g_meta[e + 0]);
            int2 m1_ = __ldg(&g_meta[e + 1]);
            int2 m2_ = __ldg(&g_meta[e + 2]);
            int2 m3_ = __ldg(&g_meta[e + 3]);
            uint2 r0 = __ldg((const uint2*)(hh_in + (size_t)(m0_.x & 0xFFFFF) * HH) + lane);
            uint2 r1 = __ldg((const uint2*)(hh_in + (size_t)(m1_.x & 0xFFFFF) * HH) + lane);
            uint2 r2 = __ldg((const uint2*)(hh_in + (size_t)(m2_.x & 0xFFFFF) * HH) + lane);
            uint2 r3 = __ldg((const uint2*)(hh_in + (size_t)(m3_.x & 0xFFFFF) * HH) + lane);
            ACC_EDGE(m0_, r0);
            ACC_EDGE(m1_, r1);
            ACC_EDGE(m2_, r2);
            ACC_EDGE(m3_, r3);
        }
        for (; e < end; e++) {
            int2 mt = __ldg(&g_meta[e]);
            uint2 rr = __ldg((const uint2*)(hh_in + (size_t)(mt.x & 0xFFFFF) * HH) + lane);
            ACC_EDGE(mt, rr);
        }
        __half* dst = sA + m * SAP + 4 * lane;
        *(__half2*)(dst + 0 * 128 + 0) = __floats2half2_rn(a0.x, a0.y);
        *(__half2*)(dst + 0 * 128 + 2) = __floats2half2_rn(a0.z, a0.w);
        *(__half2*)(dst + 1 * 128 + 0) = __floats2half2_rn(a1.x, a1.y);
        *(__half2*)(dst + 1 * 128 + 2) = __floats2half2_rn(a1.z, a1.w);
        *(__half2*)(dst + 2 * 128 + 0) = __floats2half2_rn(a2.x, a2.y);
        *(__half2*)(dst + 2 * 128 + 2) = __floats2half2_rn(a2.z, a2.w);
        *(__half2*)(dst + 3 * 128 + 0) = __floats2half2_rn(a3.x, a3.y);
        *(__half2*)(dst + 3 * 128 + 2) = __floats2half2_rn(a3.z, a3.w);
    }
#undef ACC_EDGE
    __syncthreads();

    // ---- GEMM: [TM x 640] @ [640 x 128], barrier-free; B frags register-prefetched from L2 ----
    int wn = warp;                   // warp tile: 32 rows x 16 cols
    int g = lane >> 2, t = lane & 3;
    float acc[2][2][4];
#pragma unroll
    for (int i = 0; i < 2; i++)
#pragma unroll
        for (int j = 0; j < 2; j++)
#pragma unroll
            for (int c = 0; c < 4; c++) acc[i][j][c] = 0.f;

    // per-thread base into staged weights [kc][128 n][16 k] (halves)
    const __half* bg = wB_l + (wn * 16 + g) * 16 + 2 * t;
    uint32_t Bf[2][2][2];
    Bf[0][0][0] = *(const uint32_t*)(bg);
    Bf[0][0][1] = *(const uint32_t*)(bg + 8);
    Bf[0][1][0] = *(const uint32_t*)(bg + 128);
    Bf[0][1][1] = *(const uint32_t*)(bg + 136);

#pragma unroll 2
    for (int kc = 0; kc < NC16; kc++) {
        int cur = kc & 1, nxt = cur ^ 1;
        if (kc + 1 < NC16) {
            const __half* b = bg + (size_t)(kc + 1) * 2048;
            Bf[nxt][0][0] = *(const uint32_t*)(b);
            Bf[nxt][0][1] = *(const uint32_t*)(b + 8);
            Bf[nxt][1][0] = *(const uint32_t*)(b + 128);
            Bf[nxt][1][1] = *(const uint32_t*)(b + 136);
        }
        int ka = kc * 16 + 2 * t;
#pragma unroll
        for (int mi = 0; mi < 2; mi++) {
            int R = mi * 16 + g;
            uint32_t A0 = *(const uint32_t*)&sA[R * SAP + ka];
            uint32_t A1 = *(const uint32_t*)&sA[(R + 8) * SAP + ka];
            uint32_t A2 = *(const uint32_t*)&sA[R * SAP + ka + 8];
            uint32_t A3 = *(const uint32_t*)&sA[(R + 8) * SAP + ka + 8];
#pragma unroll
            for (int ni = 0; ni < 2; ni++)
                mma_f16(acc[mi][ni], A0, A1, A2, A3, Bf[cur][ni][0], Bf[cur][ni][1]);
        }
    }
    __syncthreads();

    // ---- epilogue: stage C to smem (sA no longer needed) ----
#pragma unroll
    for (int mi = 0; mi < 2; mi++) {
        int R = mi * 16 + g;
#pragma unroll
        for (int ni = 0; ni < 2; ni++) {
            int col = wn * 16 + ni * 8 + 2 * t;
            sC[R * SCP + col]           = acc[mi][ni][0];
            sC[R * SCP + col + 1]       = acc[mi][ni][1];
            sC[(R + 8) * SCP + col]     = acc[mi][ni][2];
            sC[(R + 8) * SCP + col + 1] = acc[mi][ni][3];
        }
    }
    __syncthreads();

    // ---- bias + LayerNorm + relu + residual(fp16); write fp16 features ----
    for (int i = 0; i < 4; i++) {
        int m = warp * 4 + i;
        size_t rowo = (size_t)(m0 + m) * HH;
        float4 v = *(float4*)&sC[m * SCP + 4 * lane];
        float4 bi = __ldg(&((const float4*)bias_l)[lane]);
        v.x += bi.x; v.y += bi.y; v.z += bi.z; v.w += bi.w;
        float s = v.x + v.y + v.z + v.w;
#pragma unroll
        for (int o = 16; o; o >>= 1) s += __shfl_xor_sync(0xFFFFFFFFu, s, o);
        float mu = s * (1.0f / HH);
        float dx = v.x - mu, dy = v.y - mu, dz = v.z - mu, dw = v.w - mu;
        float q = dx * dx + dy * dy + dz * dz + dw * dw;
#pragma unroll
        for (int o = 16; o; o >>= 1) q += __shfl_xor_sync(0xFFFFFFFFu, q, o);
        float rs = rsqrtf(q * (1.0f / HH) + 1e-5f);
        float4 g4 = __ldg(&((const float4*)gam)[lane]);
        float4 b4 = __ldg(&((const float4*)bet)[lane]);
        float4 o4;
        o4.x = fmaxf(dx * rs * g4.x + b4.x, 0.f);
        o4.y = fmaxf(dy * rs * g4.y + b4.y, 0.f);
        o4.z = fmaxf(dz * rs * g4.z + b4.z, 0.f);
        o4.w = fmaxf(dw * rs * g4.w + b4.w, 0.f);
        if (residual) {
            uint2 hv = ((const uint2*)(hh_in + rowo))[lane];
            float2 h0 = __half22float2(*(__half2*)&hv.x);
            float2 h1 = __half22float2(*(__half2*)&hv.y);
            o4.x += h0.x; o4.y += h0.y; o4.z += h1.x; o4.w += h1.y;
        }
        uint2 hpk;
        *(__half2*)&hpk.x = __floats2half2_rn(o4.x, o4.y);
        *(__half2*)&hpk.y = __floats2half2_rn(o4.z, o4.w);
        ((uint2*)(hh_out + rowo))[lane] = hpk;
    }
}

// ================= head: hidden = relu(h @ W1 + b1) fp16-mma (barrier-free); out = hidden @ W2 + b2 =================
__global__ void __launch_bounds__(256, 4) k_headf(
    const __half* __restrict__ hh,
    const float* __restrict__ b1,
    const float* __restrict__ W2, const float* __restrict__ b2,
    float* __restrict__ outp)
{
    extern __shared__ __align__(16) char dyn[];
    __half* sA = (__half*)dyn;                       // [TM][SAPH] (aliased with sC)
    float*  sC = (float*)dyn;                        // [TM][SCP]
    __shared__ float sW2[HH * OUTD];
    __shared__ float sb2[OUTD];

    int tid = threadIdx.x, warp = tid >> 5, lane = tid & 31;
    int m0 = blockIdx.x * TM;

    for (int i = tid; i < HH * OUTD; i += 256) sW2[i] = W2[i];
    if (tid < OUTD) sb2[tid] = b2[tid];

    // ---- stage A: 32 rows x 128 halves ----
    for (int i = tid; i < TM * 16; i += 256) {
        int m = i >> 4, c8 = i & 15;
        *(uint4*)(sA + m * SAPH + c8 * 8) =
            ((const uint4*)(hh + (size_t)(m0 + m) * HH))[c8];
    }
    __syncthreads();

    // ---- GEMM: [32 x 128] @ [128 x 128], 8 chunks, barrier-free ----
    int wn = warp;
    int g = lane >> 2, t = lane & 3;
    float acc[2][2][4];
#pragma unroll
    for (int i = 0; i < 2; i++)
#pragma unroll
        for (int j = 0; j < 2; j++)
#pragma unroll
            for (int c = 0; c < 4; c++) acc[i][j][c] = 0.f;

    const __half* bg = g_wB1 + (wn * 16 + g) * 16 + 2 * t;
    uint32_t Bf[2][2][2];
    Bf[0][0][0] = *(const uint32_t*)(bg);
    Bf[0][0][1] = *(const uint32_t*)(bg + 8);
    Bf[0][1][0] = *(const uint32_t*)(bg + 128);
    Bf[0][1][1] = *(const uint32_t*)(bg + 136);

#pragma unroll
    for (int kc = 0; kc < 8; kc++) {
        int cur = kc & 1, nxt = cur ^ 1;
        if (kc + 1 < 8) {
            const __half* b = bg + (size_t)(kc + 1) * 2048;
            Bf[nxt][0][0] = *(const uint32_t*)(b);
            Bf[nxt][0][1] = *(const uint32_t*)(b + 8);
            Bf[nxt][1][0] = *(const uint32_t*)(b + 128);
            Bf[nxt][1][1] = *(const uint32_t*)(b + 136);
        }
        int ka = kc * 16 + 2 * t;
#pragma unroll
        for (int mi = 0; mi < 2; mi++) {
            int R = mi * 16 + g;
            uint32_t A0 = *(const uint32_t*)&sA[R * SAPH + ka];
            uint32_t A1 = *(const uint32_t*)&sA[(R + 8) * SAPH + ka];
            uint32_t A2 = *(const uint32_t*)&sA[R * SAPH + ka + 8];
            uint32_t A3 = *(const uint32_t*)&sA[(R + 8) * SAPH + ka + 8];
#pragma unroll
            for (int ni = 0; ni < 2; ni++)
                mma_f16(acc[mi][ni], A0, A1, A2, A3, Bf[cur][ni][0], Bf[cur][ni][1]);
        }
    }
    __syncthreads();

    // ---- hidden (bias + relu) -> sC (overwrites sA; all reads done) ----
#pragma unroll
    for (int mi = 0; mi < 2; mi++) {
        int R = mi * 16 + g;
#pragma unroll
        for (int ni = 0; ni < 2; ni++) {
            int col = wn * 16 + ni * 8 + 2 * t;
            float b0 = b1[col], bb1 = b1[col + 1];
            sC[R * SCP + col]           = fmaxf(acc[mi][ni][0] + b0, 0.f);
            sC[R * SCP + col + 1]       = fmaxf(acc[mi][ni][1] + bb1, 0.f);
            sC[(R + 8) * SCP + col]     = fmaxf(acc[mi][ni][2] + b0, 0.f);
            sC[(R + 8) * SCP + col + 1] = fmaxf(acc[mi][ni][3] + bb1, 0.f);
        }
    }
    __syncthreads();

    // ---- tail: out[row, 0..7] = hidden[row,:] @ W2 + b2 ----
    {
        int row = tid >> 3;          // 0..31
        int col = tid & 7;
        float o = sb2[col];
#pragma unroll 4
        for (int k = 0; k < HH; k++)
            o += sC[row * SCP + k] * sW2[k * OUTD + col];
        outp[(size_t)(m0 + row) * OUTD + col] = o;
    }
}

// ---------------- launch ----------------
extern "C" void kernel_launch(void* const* d_in, const int* in_sizes, int n_in,
                              void* d_out, int out_size) {
    const float* x     = (const float*)d_in[0];
    const void*  ei    = d_in[1];
    const void*  et    = d_in[2];
    const float* W_in  = (const float*)d_in[3];
    const float* b_in  = (const float*)d_in[4];
    const float* basis = (const float*)d_in[5];
    const float* comp  = (const float*)d_in[6];
    const float* root  = (const float*)d_in[7];
    const float* bias  = (const float*)d_in[8];
    const float* ln_g  = (const float*)d_in[9];
    const float* ln_b  = (const float*)d_in[10];
    const float* W1    = (const float*)d_in[11];
    const float* b1    = (const float*)d_in[12];
    const float* W2    = (const float*)d_in[13];
    const float* b2    = (const float*)d_in[14];

    void *p_hh0, *p_hh1, *p_wB;
    cudaGetSymbolAddress(&p_hh0, g_hh0);
    cudaGetSymbolAddress(&p_hh1, g_hh1);
    cudaGetSymbolAddress(&p_wB,  g_wB);
    cudaFuncSetAttribute(k_layer, cudaFuncAttributeMaxDynamicSharedMemorySize, SMEM_LAYER);
    cudaFuncSetAttribute(k_headf, cudaFuncAttributeMaxDynamicSharedMemorySize, SMEM_HEADF);

    // ---- one-time preprocessing ----
    k_detect<<<1, 256>>>((const int*)ei);
    k_zero_cnt<<<(NN * RR + 255) / 256, 256>>>();
    k_prep_count<<<EE / 256, 256>>>(ei, et);
    k_ps1<<<NN / 256, 256>>>();
    k_ps2<<<1, 512>>>();
    k_ps3<<<NN / 256, 256>>>();
    k_csr_scatter<<<EE / 256, 256>>>(ei, et);
    k_wconv<<<(LL * NC16 * 128 * 16 + 255) / 256, 256>>>(basis, root);
    k_wconvh<<<(8 * 128 * 16 + 255) / 256, 256>>>(W1);
    k_inproj<<<NN / 8, 128>>>(x, W_in, b_in);

    // ---- fused layers (ping-pong fp16 features) ----
    __half* hhb[2] = {(__half*)p_hh0, (__half*)p_hh1};
    for (int i = 0; i < LL; i++) {
        k_layer<<<NN / TM, 256, SMEM_LAYER>>>(
            hhb[i & 1], hhb[(i + 1) & 1],
            (const __half*)p_wB + (size_t)i * NC16 * 128 * 16,
            comp + i * RR * BB,
            bias + i * HH, ln_g + i * HH, ln_b + i * HH, i > 0 ? 1 : 0);
    }

    // ---- fp16 head ----
    k_headf<<<NN / TM, 256, SMEM_HEADF>>>(hhb[LL & 1], b1, W2, b2, (float*)d_out);
}

// round 16
// speedup vs baseline: 1.6704x; 1.0198x over previous
#include <cuda_runtime.h>
#include <cuda_fp16.h>
#include <cstdint>

#define NN   131072
#define EE   2097152
#define FF   32
#define HH   128
#define RR   10
#define BB   4
#define LL   3
#define OUTD 8

#define TM   32               // layer-kernel block rows (dst nodes)
#define SAP  648              // sA k-stride in halves (640 + 8 pad)
#define SCP  132              // sC row stride in floats
#define NC16 40               // 16-wide K chunks (640 total)
#define SMEM_LAYER (TM * SAP * 2)                    // 41472 B
#define SAPH 136              // head sA k-stride in halves (128 + 8 pad)
#define SMEM_HEADF (TM * SCP * 4)                    // 16896 B

// ---------------- device scratch ----------------
__device__ __half g_hh0[(size_t)NN * HH];   // fp16 features (ping)
__device__ __half g_hh1[(size_t)NN * HH];   // fp16 features (pong)
__device__ __half g_wB [(size_t)LL * NC16 * 128 * 16]; // staged fp16 layer weights
__device__ __half g_wB1[(size_t)8 * 128 * 16];         // staged fp16 W1 (head)
__device__ float  g_cnt[NN * RR];
__device__ int    g_row[NN + 1];
__device__ int    g_bsum[512];
__device__ int    g_cursor[NN];
__device__ int2   g_meta [EE];         // dst-sorted {src|rel<<20, bits(1/cnt)}
__device__ int4   g_meta4[EE];         // per-layer {src, c01_h2, c23_h2, 0}
__device__ int    g_is64;

// ---------------- helpers ----------------
__device__ __forceinline__ void mma_f16(float* c,
                                        uint32_t a0, uint32_t a1, uint32_t a2, uint32_t a3,
                                        uint32_t b0, uint32_t b1) {
    asm volatile(
        "mma.sync.aligned.m16n8k16.row.col.f32.f16.f16.f32 "
        "{%0,%1,%2,%3}, {%4,%5,%6,%7}, {%8,%9}, {%0,%1,%2,%3};"
        : "+f"(c[0]), "+f"(c[1]), "+f"(c[2]), "+f"(c[3])
        : "r"(a0), "r"(a1), "r"(a2), "r"(a3), "r"(b0), "r"(b1));
}

// ---------------- dtype detect ----------------
__global__ void k_detect(const int* __restrict__ ei) {
    __shared__ int cnt;
    if (threadIdx.x == 0) cnt = 0;
    __syncthreads();
    if (ei[threadIdx.x * 2 + 1] != 0) atomicAdd(&cnt, 1);
    __syncthreads();
    if (threadIdx.x == 0) g_is64 = (cnt == 0) ? 1 : 0;
}

__global__ void k_zero_cnt() {
    int i = blockIdx.x * blockDim.x + threadIdx.x;
    if (i < NN * RR) g_cnt[i] = 0.0f;
}

// ---------------- decode + per-(dst,rel) count ----------------
__global__ void k_prep_count(const void* __restrict__ ei_raw, const void* __restrict__ et_raw) {
    int e = blockIdx.x * blockDim.x + threadIdx.x;
    if (e >= EE) return;
    int d, t;
    if (g_is64) {
        const long long* ei = (const long long*)ei_raw;
        const long long* et = (const long long*)et_raw;
        d = (int)ei[(size_t)EE + e];
        t = (int)et[e];
    } else {
        const int* ei = (const int*)ei_raw;
        const int* et = (const int*)et_raw;
        d = ei[EE + e];
        t = et[e];
    }
    atomicAdd(&g_cnt[d * RR + t], 1.0f);
}

// ---------------- prefix scan over node degrees (derived from g_cnt) ----------------
__global__ void k_ps1() {
    __shared__ int sh[256];
    int i = blockIdx.x * 256 + threadIdx.x;
    int v = 0;
#pragma unroll
    for (int r = 0; r < RR; r++) v += (int)g_cnt[i * RR + r];
    sh[threadIdx.x] = v;
    __syncthreads();
#pragma unroll
    for (int o = 1; o < 256; o <<= 1) {
        int t = (threadIdx.x >= o) ? sh[threadIdx.x - o] : 0;
        __syncthreads();
        sh[threadIdx.x] += t;
        __syncthreads();
    }
    g_row[i] = sh[threadIdx.x] - v;
    if (threadIdx.x == 255) g_bsum[blockIdx.x] = sh[255];
}

__global__ void k_ps2() {
    __shared__ int sh[512];
    int v = g_bsum[threadIdx.x];
    sh[threadIdx.x] = v;
    __syncthreads();
#pragma unroll
    for (int o = 1; o < 512; o <<= 1) {
        int t = (threadIdx.x >= o) ? sh[threadIdx.x - o] : 0;
        __syncthreads();
        sh[threadIdx.x] += t;
        __syncthreads();
    }
    g_bsum[threadIdx.x] = sh[threadIdx.x] - v;
}

__global__ void k_ps3() {
    int i = blockIdx.x * 256 + threadIdx.x;
    int r = g_row[i] + g_bsum[i >> 8];
    g_row[i] = r;
    g_cursor[i] = r;
    if (i == 0) g_row[NN] = EE;
}

// ---------------- CSR scatter (re-decodes raw edges) ----------------
__global__ void k_csr_scatter(const void* __restrict__ ei_raw, const void* __restrict__ et_raw) {
    int e = blockIdx.x * blockDim.x + threadIdx.x;
    if (e >= EE) return;
    int s, d, t;
    if (g_is64) {
        const long long* ei = (const long long*)ei_raw;
        const long long* et = (const long long*)et_raw;
        s = (int)ei[e];
        d = (int)ei[(size_t)EE + e];
        t = (int)et[e];
    } else {
        const int* ei = (const int*)ei_raw;
        const int* et = (const int*)et_raw;
        s = ei[e];
        d = ei[EE + e];
        t = et[e];
    }
    int pos = atomicAdd(&g_cursor[d], 1);
    float inv = 1.0f / fmaxf(g_cnt[d * RR + t], 1.0f);
    g_meta[pos] = make_int2(s | (t << 20), __float_as_int(inv));
}

// ---------------- per-layer coefficient pack ----------------
__global__ void k_coef(const float* __restrict__ comp_l) {
    __shared__ float sc[RR * BB];
    if (threadIdx.x < RR * BB) sc[threadIdx.x] = comp_l[threadIdx.x];
    __syncthreads();
    int e = blockIdx.x * blockDim.x + threadIdx.x;
    if (e >= EE) return;
    int2 m = g_meta[e];
    int src = m.x & 0xFFFFF;
    int r   = m.x >> 20;
    float inv = __int_as_float(m.y);
    __half2 c01 = __floats2half2_rn(sc[r * BB + 0] * inv, sc[r * BB + 1] * inv);
    __half2 c23 = __floats2half2_rn(sc[r * BB + 2] * inv, sc[r * BB + 3] * inv);
    int4 o;
    o.x = src;
    o.y = *reinterpret_cast<int*>(&c01);
    o.z = *reinterpret_cast<int*>(&c23);
    o.w = 0;
    g_meta4[e] = o;
}

// ---------------- weight preconvert: basis||root -> staged fp16 [NC16][128][16] ----------------
__global__ void k_wconv(const float* __restrict__ basis, const float* __restrict__ root) {
    int idx = blockIdx.x * blockDim.x + threadIdx.x;
    if (idx >= LL * NC16 * 128 * 16) return;
    int l   = idx / (NC16 * 128 * 16);
    int rem = idx % (NC16 * 128 * 16);
    int kc  = rem >> 11;
    int n   = (rem >> 4) & 127;
    int kr  = rem & 15;
    int kg  = kc * 16 + kr;
    float v = (kg < 512) ? basis[(size_t)l * 512 * HH + (size_t)kg * HH + n]
                         : root [(size_t)l * HH * HH + (size_t)(kg - 512) * HH + n];
    g_wB[idx] = __float2half_rn(v);
}

// ---------------- W1 preconvert -> staged fp16 [8][128][16] ----------------
__global__ void k_wconvh(const float* __restrict__ W1) {
    int idx = blockIdx.x * blockDim.x + threadIdx.x;
    if (idx >= 8 * 128 * 16) return;
    int kc = idx >> 11;
    int n  = (idx >> 4) & 127;
    int kr = idx & 15;
    g_wB1[idx] = __float2half_rn(W1[(size_t)(kc * 16 + kr) * HH + n]);
}

// ---------------- input projection (fp16 features only) ----------------
__global__ void k_inproj(const float* __restrict__ x, const float* __restrict__ W,
                         const float* __restrict__ b) {
    __shared__ float Ws[FF * HH];
    __shared__ float xs[8][FF];
    int tid = threadIdx.x;
    for (int i = tid; i < FF * HH; i += 128) Ws[i] = W[i];
    int n0 = blockIdx.x * 8;
    for (int i = tid; i < 8 * FF; i += 128) xs[i / FF][i % FF] = x[(size_t)n0 * FF + i];
    __syncthreads();
    float bj = b[tid];
#pragma unroll
    for (int u = 0; u < 8; u++) {
        float acc = bj;
#pragma unroll
        for (int k = 0; k < FF; k++) acc += xs[u][k] * Ws[k * HH + tid];
        g_hh0[(size_t)(n0 + u) * HH + tid] = __float2half_rn(acc);
    }
}

// ================= fused RGCN layer (TM=32, 4/SM, HFMA2 agg, barrier-free GEMM) =================
__global__ void __launch_bounds__(256, 4) k_layer(
    const __half* __restrict__ hh_in, __half* __restrict__ hh_out,
    const __half* __restrict__ wB_l,
    const float* __restrict__ bias_l,
    const float* __restrict__ gam, const float* __restrict__ bet, int residual)
{
    extern __shared__ __align__(16) char dyn[];
    __half* sA = (__half*)dyn;                       // [TM][SAP]
    float*  sC = (float*)dyn;                        // epilogue reuse [TM][SCP]

    int tid = threadIdx.x, warp = tid >> 5, lane = tid & 31;
    int m0 = blockIdx.x * TM;

    // ---- stage h (root planes 512..639) from fp16 features ----
    for (int i = tid; i < TM * 16; i += 256) {
        int m = i >> 4, c8 = i & 15;
        *(uint4*)(sA + m * SAP + 512 + c8 * 8) =
            ((const uint4*)(hh_in + (size_t)(m0 + m) * HH))[c8];
    }
    __syncthreads();

    // ---- aggregation: 4 nodes per warp, half2 accumulators, 4-way unrolled ----
#define ACC4(q, rr)                                                           \
    {                                                                         \
        __half2 c01 = *reinterpret_cast<__half2*>(&q.y);                      \
        __half2 c23 = *reinterpret_cast<__half2*>(&q.z);                      \
        __half2 v01 = *reinterpret_cast<__half2*>(&rr.x);                     \
        __half2 v23 = *reinterpret_cast<__half2*>(&rr.y);                     \
        ab00 = __hfma2(__low2half2(c01),  v01, ab00);                         \
        ab01 = __hfma2(__low2half2(c01),  v23, ab01);                         \
        ab10 = __hfma2(__high2half2(c01), v01, ab10);                         \
        ab11 = __hfma2(__high2half2(c01), v23, ab11);                         \
        ab20 = __hfma2(__low2half2(c23),  v01, ab20);                         \
        ab21 = __hfma2(__low2half2(c23),  v23, ab21);                         \
        ab30 = __hfma2(__high2half2(c23), v01, ab30);                         \
        ab31 = __hfma2(__high2half2(c23), v23, ab31);                         \
    }

    for (int ii = 0; ii < 4; ii++) {
        int m = warp * 4 + ii;
        int node = m0 + m;
        int beg = g_row[node], end = g_row[node + 1];
        __half2 z = __float2half2_rn(0.f);
        __half2 ab00 = z, ab01 = z, ab10 = z, ab11 = z;
        __half2 ab20 = z, ab21 = z, ab30 = z, ab31 = z;
        int e = beg;
        for (; e + 4 <= end; e += 4) {
            int4 q0 = __ldg(&g_meta4[e + 0]);
            int4 q1 = __ldg(&g_meta4[e + 1]);
            int4 q2 = __ldg(&g_meta4[e + 2]);
            int4 q3 = __ldg(&g_meta4[e + 3]);
            uint2 r0 = __ldg((const uint2*)(hh_in + (size_t)q0.x * HH) + lane);
            uint2 r1 = __ldg((const uint2*)(hh_in + (size_t)q1.x * HH) + lane);
            uint2 r2 = __ldg((const uint2*)(hh_in + (size_t)q2.x * HH) + lane);
            uint2 r3 = __ldg((const uint2*)(hh_in + (size_t)q3.x * HH) + lane);
            ACC4(q0, r0);
            ACC4(q1, r1);
            ACC4(q2, r2);
            ACC4(q3, r3);
        }
        for (; e < end; e++) {
            int4 q = __ldg(&g_meta4[e]);
            uint2 rr = __ldg((const uint2*)(hh_in + (size_t)q.x * HH) + lane);
            ACC4(q, rr);
        }
        __half* dst = sA + m * SAP + 4 * lane;
        *(__half2*)(dst + 0 * 128 + 0) = ab00;
        *(__half2*)(dst + 0 * 128 + 2) = ab01;
        *(__half2*)(dst + 1 * 128 + 0) = ab10;
        *(__half2*)(dst + 1 * 128 + 2) = ab11;
        *(__half2*)(dst + 2 * 128 + 0) = ab20;
        *(__half2*)(dst + 2 * 128 + 2) = ab21;
        *(__half2*)(dst + 3 * 128 + 0) = ab30;
        *(__half2*)(dst + 3 * 128 + 2) = ab31;
    }
#undef ACC4
    __syncthreads();

    // ---- GEMM: [TM x 640] @ [640 x 128], barrier-free; B frags register-prefetched from L2 ----
    int wn = warp;                   // warp tile: 32 rows x 16 cols
    int g = lane >> 2, t = lane & 3;
    float acc[2][2][4];
#pragma unroll
    for (int i = 0; i < 2; i++)
#pragma unroll
        for (int j = 0; j < 2; j++)
#pragma unroll
            for (int c = 0; c < 4; c++) acc[i][j][c] = 0.f;

    const __half* bg = wB_l + (wn * 16 + g) * 16 + 2 * t;
    uint32_t Bf[2][2][2];
    Bf[0][0][0] = *(const uint32_t*)(bg);
    Bf[0][0][1] = *(const uint32_t*)(bg + 8);
    Bf[0][1][0] = *(const uint32_t*)(bg + 128);
    Bf[0][1][1] = *(const uint32_t*)(bg + 136);

#pragma unroll 2
    for (int kc = 0; kc < NC16; kc++) {
        int cur = kc & 1, nxt = cur ^ 1;
        if (kc + 1 < NC16) {
            const __half* b = bg + (size_t)(kc + 1) * 2048;
            Bf[nxt][0][0] = *(const uint32_t*)(b);
            Bf[nxt][0][1] = *(const uint32_t*)(b + 8);
            Bf[nxt][1][0] = *(const uint32_t*)(b + 128);
            Bf[nxt][1][1] = *(const uint32_t*)(b + 136);
        }
        int ka = kc * 16 + 2 * t;
#pragma unroll
        for (int mi = 0; mi < 2; mi++) {
            int R = mi * 16 + g;
            uint32_t A0 = *(const uint32_t*)&sA[R * SAP + ka];
            uint32_t A1 = *(const uint32_t*)&sA[(R + 8) * SAP + ka];
            uint32_t A2 = *(const uint32_t*)&sA[R * SAP + ka + 8];
            uint32_t A3 = *(const uint32_t*)&sA[(R + 8) * SAP + ka + 8];
#pragma unroll
            for (int ni = 0; ni < 2; ni++)
                mma_f16(acc[mi][ni], A0, A1, A2, A3, Bf[cur][ni][0], Bf[cur][ni][1]);
        }
    }
    __syncthreads();

    // ---- epilogue: stage C to smem (sA no longer needed) ----
#pragma unroll
    for (int mi = 0; mi < 2; mi++) {
        int R = mi * 16 + g;
#pragma unroll
        for (int ni = 0; ni < 2; ni++) {
            int col = wn * 16 + ni * 8 + 2 * t;
            sC[R * SCP + col]           = acc[mi][ni][0];
            sC[R * SCP + col + 1]       = acc[mi][ni][1];
            sC[(R + 8) * SCP + col]     = acc[mi][ni][2];
            sC[(R + 8) * SCP + col + 1] = acc[mi][ni][3];
        }
    }
    __syncthreads();

    // ---- bias + LayerNorm + relu + residual(fp16); write fp16 features ----
    for (int i = 0; i < 4; i++) {
        int m = warp * 4 + i;
        size_t rowo = (size_t)(m0 + m) * HH;
        float4 v = *(float4*)&sC[m * SCP + 4 * lane];
        float4 bi = __ldg(&((const float4*)bias_l)[lane]);
        v.x += bi.x; v.y += bi.y; v.z += bi.z; v.w += bi.w;
        float s = v.x + v.y + v.z + v.w;
#pragma unroll
        for (int o = 16; o; o >>= 1) s += __shfl_xor_sync(0xFFFFFFFFu, s, o);
        float mu = s * (1.0f / HH);
        float dx = v.x - mu, dy = v.y - mu, dz = v.z - mu, dw = v.w - mu;
        float q = dx * dx + dy * dy + dz * dz + dw * dw;
#pragma unroll
        for (int o = 16; o; o >>= 1) q += __shfl_xor_sync(0xFFFFFFFFu, q, o);
        float rs = rsqrtf(q * (1.0f / HH) + 1e-5f);
        float4 g4 = __ldg(&((const float4*)gam)[lane]);
        float4 b4 = __ldg(&((const float4*)bet)[lane]);
        float4 o4;
        o4.x = fmaxf(dx * rs * g4.x + b4.x, 0.f);
        o4.y = fmaxf(dy * rs * g4.y + b4.y, 0.f);
        o4.z = fmaxf(dz * rs * g4.z + b4.z, 0.f);
        o4.w = fmaxf(dw * rs * g4.w + b4.w, 0.f);
        if (residual) {
            uint2 hv = ((const uint2*)(hh_in + rowo))[lane];
            float2 h0 = __half22float2(*(__half2*)&hv.x);
            float2 h1 = __half22float2(*(__half2*)&hv.y);
            o4.x += h0.x; o4.y += h0.y; o4.z += h1.x; o4.w += h1.y;
        }
        uint2 hpk;
        *(__half2*)&hpk.x = __floats2half2_rn(o4.x, o4.y);
        *(__half2*)&hpk.y = __floats2half2_rn(o4.z, o4.w);
        ((uint2*)(hh_out + rowo))[lane] = hpk;
    }
}

// ================= head: hidden = relu(h @ W1 + b1) fp16-mma (barrier-free); out = hidden @ W2 + b2 =================
__global__ void __launch_bounds__(256, 4) k_headf(
    const __half* __restrict__ hh,
    const float* __restrict__ b1,
    const float* __restrict__ W2, const float* __restrict__ b2,
    float* __restrict__ outp)
{
    extern __shared__ __align__(16) char dyn[];
    __half* sA = (__half*)dyn;                       // [TM][SAPH] (aliased with sC)
    float*  sC = (float*)dyn;                        // [TM][SCP]
    __shared__ float sW2[HH * OUTD];
    __shared__ float sb2[OUTD];

    int tid = threadIdx.x, warp = tid >> 5, lane = tid & 31;
    int m0 = blockIdx.x * TM;

    for (int i = tid; i < HH * OUTD; i += 256) sW2[i] = W2[i];
    if (tid < OUTD) sb2[tid] = b2[tid];

    // ---- stage A: 32 rows x 128 halves ----
    for (int i = tid; i < TM * 16; i += 256) {
        int m = i >> 4, c8 = i & 15;
        *(uint4*)(sA + m * SAPH + c8 * 8) =
            ((const uint4*)(hh + (size_t)(m0 + m) * HH))[c8];
    }
    __syncthreads();

    // ---- GEMM: [32 x 128] @ [128 x 128], 8 chunks, barrier-free ----
    int wn = warp;
    int g = lane >> 2, t = lane & 3;
    float acc[2][2][4];
#pragma unroll
    for (int i = 0; i < 2; i++)
#pragma unroll
        for (int j = 0; j < 2; j++)
#pragma unroll
            for (int c = 0; c < 4; c++) acc[i][j][c] = 0.f;

    const __half* bg = g_wB1 + (wn * 16 + g) * 16 + 2 * t;
    uint32_t Bf[2][2][2];
    Bf[0][0][0] = *(const uint32_t*)(bg);
    Bf[0][0][1] = *(const uint32_t*)(bg + 8);
    Bf[0][1][0] = *(const uint32_t*)(bg + 128);
    Bf[0][1][1] = *(const uint32_t*)(bg + 136);

#pragma unroll
    for (int kc = 0; kc < 8; kc++) {
        int cur = kc & 1, nxt = cur ^ 1;
        if (kc + 1 < 8) {
            const __half* b = bg + (size_t)(kc + 1) * 2048;
            Bf[nxt][0][0] = *(const uint32_t*)(b);
            Bf[nxt][0][1] = *(const uint32_t*)(b + 8);
            Bf[nxt][1][0] = *(const uint32_t*)(b + 128);
            Bf[nxt][1][1] = *(const uint32_t*)(b + 136);
        }
        int ka = kc * 16 + 2 * t;
#pragma unroll
        for (int mi = 0; mi < 2; mi++) {
            int R = mi * 16 + g;
            uint32_t A0 = *(const uint32_t*)&sA[R * SAPH + ka];
            uint32_t A1 = *(const uint32_t*)&sA[(R + 8) * SAPH + ka];
            uint32_t A2 = *(const uint32_t*)&sA[R * SAPH + ka + 8];
            uint32_t A3 = *(const uint32_t*)&sA[(R + 8) * SAPH + ka + 8];
#pragma unroll
            for (int ni = 0; ni < 2; ni++)
                mma_f16(acc[mi][ni], A0, A1, A2, A3, Bf[cur][ni][0], Bf[cur][ni][1]);
        }
    }
    __syncthreads();

    // ---- hidden (bias + relu) -> sC (overwrites sA; all reads done) ----
#pragma unroll
    for (int mi = 0; mi < 2; mi++) {
        int R = mi * 16 + g;
#pragma unroll
        for (int ni = 0; ni < 2; ni++) {
            int col = wn * 16 + ni * 8 + 2 * t;
            float b0 = b1[col], bb1 = b1[col + 1];
            sC[R * SCP + col]           = fmaxf(acc[mi][ni][0] + b0, 0.f);
            sC[R * SCP + col + 1]       = fmaxf(acc[mi][ni][1] + bb1, 0.f);
            sC[(R + 8) * SCP + col]     = fmaxf(acc[mi][ni][2] + b0, 0.f);
            sC[(R + 8) * SCP + col + 1] = fmaxf(acc[mi][ni][3] + bb1, 0.f);
        }
    }
    __syncthreads();

    // ---- tail: out[row, 0..7] = hidden[row,:] @ W2 + b2 ----
    {
        int row = tid >> 3;          // 0..31
        int col = tid & 7;
        float o = sb2[col];
#pragma unroll 4
        for (int k = 0; k < HH; k++)
            o += sC[row * SCP + k] * sW2[k * OUTD + col];
        outp[(size_t)(m0 + row) * OUTD + col] = o;
    }
}

// ---------------- launch ----------------
extern "C" void kernel_launch(void* const* d_in, const int* in_sizes, int n_in,
                              void* d_out, int out_size) {
    const float* x     = (const float*)d_in[0];
    const void*  ei    = d_in[1];
    const void*  et    = d_in[2];
    const float* W_in  = (const float*)d_in[3];
    const float* b_in  = (const float*)d_in[4];
    const float* basis = (const float*)d_in[5];
    const float* comp  = (const float*)d_in[6];
    const float* root  = (const float*)d_in[7];
    const float* bias  = (const float*)d_in[8];
    const float* ln_g  = (const float*)d_in[9];
    const float* ln_b  = (const float*)d_in[10];
    const float* W1    = (const float*)d_in[11];
    const float* b1    = (const float*)d_in[12];
    const float* W2    = (const float*)d_in[13];
    const float* b2    = (const float*)d_in[14];

    void *p_hh0, *p_hh1, *p_wB;
    cudaGetSymbolAddress(&p_hh0, g_hh0);
    cudaGetSymbolAddress(&p_hh1, g_hh1);
    cudaGetSymbolAddress(&p_wB,  g_wB);
    cudaFuncSetAttribute(k_layer, cudaFuncAttributeMaxDynamicSharedMemorySize, SMEM_LAYER);
    cudaFuncSetAttribute(k_headf, cudaFuncAttributeMaxDynamicSharedMemorySize, SMEM_HEADF);

    // ---- one-time preprocessing ----
    k_detect<<<1, 256>>>((const int*)ei);
    k_zero_cnt<<<(NN * RR + 255) / 256, 256>>>();
    k_prep_count<<<EE / 256, 256>>>(ei, et);
    k_ps1<<<NN / 256, 256>>>();
    k_ps2<<<1, 512>>>();
    k_ps3<<<NN / 256, 256>>>();
    k_csr_scatter<<<EE / 256, 256>>>(ei, et);
    k_wconv<<<(LL * NC16 * 128 * 16 + 255) / 256, 256>>>(basis, root);
    k_wconvh<<<(8 * 128 * 16 + 255) / 256, 256>>>(W1);
    k_inproj<<<NN / 8, 128>>>(x, W_in, b_in);

    // ---- fused layers (ping-pong fp16 features) ----
    __half* hhb[2] = {(__half*)p_hh0, (__half*)p_hh1};
    for (int i = 0; i < LL; i++) {
        k_coef<<<EE / 256, 256>>>(comp + i * RR * BB);
        k_layer<<<NN / TM, 256, SMEM_LAYER>>>(
            hhb[i & 1], hhb[(i + 1) & 1],
            (const __half*)p_wB + (size_t)i * NC16 * 128 * 16,
            bias + i * HH, ln_g + i * HH, ln_b + i * HH, i > 0 ? 1 : 0);
    }

    // ---- fp16 head ----
    k_headf<<<NN / TM, 256, SMEM_HEADF>>>(hhb[LL & 1], b1, W2, b2, (float*)d_out);
}